// round 6
// baseline (speedup 1.0000x reference)
#include <cuda_runtime.h>
#include <cstdint>
#include <math.h>

// Problem constants (from reference): B=128 episodes, L=512 pad, D=512 dims.
#define NB 128
#define NL 512
#define ND 512
#define TILE 16
#define ITMAX 64
#define CG_TOL 1e-6f

// Scratch (__device__ globals; no allocations allowed)
__device__ int   g_sup_idx[NB][NL];
__device__ int   g_sup_lab[NB][NL];
__device__ int   g_qry_idx[NB][NL];
__device__ int   g_cnt[NB][4];        // [0]=ns, [1]=np, [2]=nq
__device__ float g_mu[NB][3][ND];     // task, pos, neg means
__device__ float g_rr[NB][2][ND];     // r_pos, r_neg  (= M^{-1} @ 1)
__device__ float g_sc[NB][4];         // mu_p·r_p, sum(mu_p), mu_n·r_n, sum(mu_n)

// ---------------------------------------------------------------------------
// Kernel 1: segmentation. batch_index is sorted, so each episode is a
// contiguous range; stable split into support/query preserving order.
// One warp per episode, ballot-based rank computation.
// ---------------------------------------------------------------------------
__global__ void seg_kernel(const int* __restrict__ bidx, const int* __restrict__ isq,
                           const int* __restrict__ labels, int N) {
  int b = blockIdx.x;
  int lane = threadIdx.x;
  int start = 0, end = 0;
  if (lane == 0) {
    int lo = 0, hi = N;
    while (lo < hi) { int m = (lo + hi) >> 1; if (bidx[m] < b) lo = m + 1; else hi = m; }
    start = lo; hi = N;
    while (lo < hi) { int m = (lo + hi) >> 1; if (bidx[m] <= b) lo = m + 1; else hi = m; }
    end = lo;
  }
  start = __shfl_sync(0xffffffffu, start, 0);
  end   = __shfl_sync(0xffffffffu, end, 0);

  int sbase = 0, qbase = 0, pcnt = 0;
  for (int k0 = start; k0 < end; k0 += 32) {
    int k = k0 + lane;
    bool valid = k < end;
    int q  = valid ? isq[k]    : 0;
    int lb = valid ? labels[k] : 0;
    unsigned mq = __ballot_sync(0xffffffffu, valid && q != 0);
    unsigned ms = __ballot_sync(0xffffffffu, valid && q == 0);
    unsigned mp = __ballot_sync(0xffffffffu, valid && q == 0 && lb != 0);
    unsigned lt = (1u << lane) - 1u;
    if (valid) {
      if (q != 0) {
        int r = qbase + __popc(mq & lt);
        if (r < NL) g_qry_idx[b][r] = k;
      } else {
        int r = sbase + __popc(ms & lt);
        if (r < NL) { g_sup_idx[b][r] = k; g_sup_lab[b][r] = lb; }
      }
    }
    qbase += __popc(mq); sbase += __popc(ms); pcnt += __popc(mp);
  }
  if (lane == 0) {
    g_cnt[b][0] = min(sbase, NL);
    g_cnt[b][1] = pcnt;
    g_cnt[b][2] = min(qbase, NL);
  }
}

// ---------------------------------------------------------------------------
// Kernel 2: per-episode means (task / pos / neg). One CTA per episode,
// thread d owns dimension d; coalesced row reads. Also warms L2 with the
// support rows the CG kernel will re-read.
// ---------------------------------------------------------------------------
__global__ void mean_kernel(const float* __restrict__ X) {
  int b = blockIdx.x, d = threadIdx.x;
  int ns = g_cnt[b][0], np = g_cnt[b][1];
  float s = 0.f, sp = 0.f;
  for (int j = 0; j < ns; j++) {
    int idx = g_sup_idx[b][j];
    int lb  = g_sup_lab[b][j];
    float v = X[(size_t)idx * ND + d];
    s += v;
    if (lb) sp += v;
  }
  g_mu[b][0][d] = s / (float)ns;
  g_mu[b][1][d] = sp / (float)np;
  g_mu[b][2][d] = (s - sp) / (float)(ns - np);
}

// ---------------------------------------------------------------------------
// Block reduction of 4 values across 512 threads. Result broadcast to all.
// ---------------------------------------------------------------------------
__device__ __forceinline__ void red4(float* s_red, float v0, float v1, float v2, float v3,
                                     float* out) {
  #pragma unroll
  for (int o = 16; o; o >>= 1) {
    v0 += __shfl_down_sync(0xffffffffu, v0, o);
    v1 += __shfl_down_sync(0xffffffffu, v1, o);
    v2 += __shfl_down_sync(0xffffffffu, v2, o);
    v3 += __shfl_down_sync(0xffffffffu, v3, o);
  }
  int t = threadIdx.x, w = t >> 5, l = t & 31;
  if (l == 0) {
    s_red[w * 4 + 0] = v0; s_red[w * 4 + 1] = v1;
    s_red[w * 4 + 2] = v2; s_red[w * 4 + 3] = v3;
  }
  __syncthreads();
  if (t < 4) {
    float s = 0.f;
    #pragma unroll
    for (int i = 0; i < 16; i++) s += s_red[i * 4 + t];
    s_red[64 + t] = s;
  }
  __syncthreads();
  out[0] = s_red[64]; out[1] = s_red[65]; out[2] = s_red[66]; out[3] = s_red[67];
  __syncthreads();
}

// ---------------------------------------------------------------------------
// Kernel 3: fused CG for both class systems per episode.
//   M_c v = wt*Sum_j x_j(x_j.v) + wc*Sum_{j in c} x_j(x_j.v)
//           - wmt*(mu_t.v)mu_t - wmc*(mu_c.v)mu_c + 0.1 v
// Matrix-free: per iteration, stream support rows through a double-buffered
// cp.async smem tile (read from L2 once per iteration, shared by both systems).
// Pass 1: 16 warps compute per-row dots d_j = x_j.p (both systems).
// Pass 2: thread d accumulates Ap[d] += c_j d_j x_j[d] (coalesced smem).
// CG state vectors are register-resident (thread d owns component d).
// ---------------------------------------------------------------------------
#define CG_SMEM_BYTES ((2*TILE*ND + 2*ND + 2*TILE + 2*NL + NL + 80) * 4)

__global__ __launch_bounds__(512, 1) void cg_kernel(const float* __restrict__ X) {
  extern __shared__ float smem[];
  float* sT   = smem;                    // [2][TILE][ND] tile buffers
  float* s_pp = sT + 2 * TILE * ND;      // [ND]
  float* s_pn = s_pp + ND;               // [ND]
  float* s_ep = s_pn + ND;               // [TILE]
  float* s_en = s_ep + TILE;             // [TILE]
  float* s_cp = s_en + TILE;             // [NL] per-row coef (pos system)
  float* s_cn = s_cp + NL;               // [NL] per-row coef (neg system)
  int*   s_idx = (int*)(s_cn + NL);      // [NL]
  float* s_red = (float*)(s_idx + NL);   // [80]

  int b = blockIdx.x, tid = threadIdx.x, lane = tid & 31, w = tid >> 5;
  int ns = g_cnt[b][0], np = g_cnt[b][1];
  float fns = (float)ns, fnp = (float)np, fnn = (float)(ns - np);
  float wt  = 0.9f / (fns - 1.f), wmt = 0.9f * fns / (fns - 1.f);
  float wp  = 0.1f / (fnp - 1.f), wmp = 0.1f * fnp / (fnp - 1.f);
  float wn  = 0.1f / (fnn - 1.f), wmn = 0.1f * fnn / (fnn - 1.f);

  for (int j = tid; j < ns; j += 512) {
    s_idx[j] = g_sup_idx[b][j];
    int lb = g_sup_lab[b][j];
    s_cp[j] = wt + (lb ? wp : 0.f);
    s_cn[j] = wt + (lb ? 0.f : wn);
  }
  float mt  = g_mu[b][0][tid];
  float mp_ = g_mu[b][1][tid];
  float mn_ = g_mu[b][2][tid];
  // CG state (per-thread component): solve M x = 1 for pos & neg systems
  float xp = 0.f, xn = 0.f, rp = 1.f, rn = 1.f, pp = 1.f, pn = 1.f;
  float rsp = (float)ND, rsn = (float)ND;
  __syncthreads();

  int ntiles = (ns + TILE - 1) / TILE;
  int col4  = tid & 127;   // float4 column within row
  int rbase = tid >> 7;    // row group 0..3
  float o4[4];

  for (int it = 0; it < ITMAX; ++it) {
    // publish search direction + mean dot products
    s_pp[tid] = pp; s_pn[tid] = pn;
    red4(s_red, mt * pp, mp_ * pp, mt * pn, mn_ * pn, o4);
    float dtp = o4[0], dpp = o4[1], dtn = o4[2], dnn = o4[3];

    // pass-1 p slices in registers (each thread reads p[lane+32k])
    float ppr[TILE], pnr[TILE];
    #pragma unroll
    for (int k = 0; k < TILE; k++) { ppr[k] = s_pp[lane + 32 * k]; pnr[k] = s_pn[lane + 32 * k]; }

    float apr = 0.f, anr = 0.f;

    // prologue: async-load tile 0 into buffer 0
    {
      int tr0 = min(TILE, ns);
      #pragma unroll
      for (int s5 = 0; s5 < 4; s5++) {
        int r = rbase + s5 * 4;
        if (r < tr0) {
          int gj = s_idx[r];
          const float* src = X + (size_t)gj * ND + col4 * 4;
          unsigned dst = (unsigned)__cvta_generic_to_shared(&sT[r * ND + col4 * 4]);
          asm volatile("cp.async.cg.shared.global [%0], [%1], 16;" :: "r"(dst), "l"(src));
        }
      }
      asm volatile("cp.async.commit_group;");
    }

    for (int t = 0; t < ntiles; t++) {
      int buf = t & 1;
      if (t + 1 < ntiles) {
        int j0 = (t + 1) * TILE;
        int trn = min(TILE, ns - j0);
        int bufn = (t + 1) & 1;
        #pragma unroll
        for (int s5 = 0; s5 < 4; s5++) {
          int r = rbase + s5 * 4;
          if (r < trn) {
            int gj = s_idx[j0 + r];
            const float* src = X + (size_t)gj * ND + col4 * 4;
            unsigned dst = (unsigned)__cvta_generic_to_shared(&sT[bufn * TILE * ND + r * ND + col4 * 4]);
            asm volatile("cp.async.cg.shared.global [%0], [%1], 16;" :: "r"(dst), "l"(src));
          }
        }
      }
      asm volatile("cp.async.commit_group;");   // possibly-empty group keeps wait uniform
      asm volatile("cp.async.wait_group 1;");
      __syncthreads();

      int tr = min(TILE, ns - t * TILE);
      // pass 1: warp w -> row w dot products for both systems
      if (w < tr) {
        const float* row = &sT[buf * TILE * ND + w * ND];
        float ap = 0.f, an = 0.f;
        #pragma unroll
        for (int k = 0; k < TILE; k++) {
          float v = row[lane + 32 * k];
          ap += v * ppr[k]; an += v * pnr[k];
        }
        #pragma unroll
        for (int o = 16; o; o >>= 1) {
          ap += __shfl_down_sync(0xffffffffu, ap, o);
          an += __shfl_down_sync(0xffffffffu, an, o);
        }
        if (lane == 0) {
          int j = t * TILE + w;
          s_ep[w] = s_cp[j] * ap;
          s_en[w] = s_cn[j] * an;
        }
      }
      __syncthreads();
      // pass 2: thread d accumulates weighted rows (coalesced smem)
      const float* colp = &sT[buf * TILE * ND + tid];
      if (tr == TILE) {
        #pragma unroll
        for (int r2 = 0; r2 < TILE; r2++) {
          float v = colp[r2 * ND];
          apr += s_ep[r2] * v; anr += s_en[r2] * v;
        }
      } else {
        for (int r2 = 0; r2 < tr; r2++) {
          float v = colp[r2 * ND];
          apr += s_ep[r2] * v; anr += s_en[r2] * v;
        }
      }
      __syncthreads();
    }

    // rank-1 mean corrections + ridge
    float Ap_p = apr + 0.1f * pp - wmt * dtp * mt - wmp * dpp * mp_;
    float Ap_n = anr + 0.1f * pn - wmt * dtn * mt - wmn * dnn * mn_;

    red4(s_red, pp * Ap_p, pn * Ap_n, 0.f, 0.f, o4);
    float alp = rsp / o4[0], aln = rsn / o4[1];
    xp += alp * pp;  rp -= alp * Ap_p;
    xn += aln * pn;  rn -= aln * Ap_n;

    red4(s_red, rp * rp, rn * rn, 0.f, 0.f, o4);
    float bp = o4[0] / rsp, bn = o4[1] / rsn;
    rsp = o4[0]; rsn = o4[1];
    pp = rp + bp * pp;
    pn = rn + bn * pn;
    if (rsp < CG_TOL && rsn < CG_TOL) break;   // uniform across CTA
  }

  g_rr[b][0][tid] = xp;
  g_rr[b][1][tid] = xn;
  red4(s_red, mp_ * xp, mp_, mn_ * xn, mn_, o4);
  if (tid == 0) {
    g_sc[b][0] = o4[0]; g_sc[b][1] = o4[1];
    g_sc[b][2] = o4[2]; g_sc[b][3] = o4[3];
  }
}

// ---------------------------------------------------------------------------
// Kernel 4: outputs. maha = (q·r - mu·r) * (sum(q) - sum(mu)); warp per query
// row; zero-fill masked rows (output is poisoned 0xAA before timing).
// ---------------------------------------------------------------------------
__global__ void out_kernel(const float* __restrict__ X, const float* __restrict__ log_scale,
                           float* __restrict__ out) {
  __shared__ float s_rp[ND];
  __shared__ float s_rn[ND];
  __shared__ float s_s[8];
  int b = blockIdx.x, tid = threadIdx.x;
  for (int i = tid; i < ND; i += 256) { s_rp[i] = g_rr[b][0][i]; s_rn[i] = g_rr[b][1][i]; }
  if (tid < 4) s_s[tid] = g_sc[b][tid];
  if (tid == 4) s_s[4] = expf(log_scale[0]);
  __syncthreads();
  int nq = g_cnt[b][2];
  int w = tid >> 5, lane = tid & 31;
  for (int i = w; i < NL; i += 8) {
    if (i < nq) {
      int gj = g_qry_idx[b][i];
      const float* q = X + (size_t)gj * ND;
      float aqr = 0.f, aqn = 0.f, aqs = 0.f;
      #pragma unroll
      for (int k = 0; k < 16; k++) {
        float v = q[lane + 32 * k];
        aqr += v * s_rp[lane + 32 * k];
        aqn += v * s_rn[lane + 32 * k];
        aqs += v;
      }
      #pragma unroll
      for (int o = 16; o; o >>= 1) {
        aqr += __shfl_down_sync(0xffffffffu, aqr, o);
        aqn += __shfl_down_sync(0xffffffffu, aqn, o);
        aqs += __shfl_down_sync(0xffffffffu, aqs, o);
      }
      if (lane == 0) {
        float sc = s_s[4];
        float sp = aqr - s_s[0], tp = aqs - s_s[1];
        float sn = aqn - s_s[2], tn = aqs - s_s[3];
        size_t o0 = ((size_t)b * NL + i) * 2;
        out[o0]     = sn * tn * sc;   // neg logit
        out[o0 + 1] = sp * tp * sc;   // pos logit
      }
    } else if (lane == 0) {
      size_t o0 = ((size_t)b * NL + i) * 2;
      out[o0] = 0.f; out[o0 + 1] = 0.f;
    }
  }
}

// ---------------------------------------------------------------------------
// Inputs (metadata order): graph_reprs f32[N*512], log_scale f32[1],
// labels i32[N], is_query i32[N], batch_index i32[N] (sorted).
// Output: f32[128*512*2].
// ---------------------------------------------------------------------------
extern "C" void kernel_launch(void* const* d_in, const int* in_sizes, int n_in,
                              void* d_out, int out_size) {
  const float* X      = (const float*)d_in[0];
  const float* logsc  = (const float*)d_in[1];
  const int*   labels = (const int*)d_in[2];
  const int*   isq    = (const int*)d_in[3];
  const int*   bidx   = (const int*)d_in[4];
  int N = in_sizes[2];

  cudaFuncSetAttribute(cg_kernel, cudaFuncAttributeMaxDynamicSharedMemorySize, CG_SMEM_BYTES);

  seg_kernel<<<NB, 32>>>(bidx, isq, labels, N);
  mean_kernel<<<NB, ND>>>(X);
  cg_kernel<<<NB, ND, CG_SMEM_BYTES>>>(X);
  out_kernel<<<NB, 256>>>(X, logsc, (float*)d_out);
}

// round 11
// speedup vs baseline: 1.3063x; 1.3063x over previous
#include <cuda_runtime.h>
#include <cstdint>
#include <math.h>

// Problem constants: B=128 episodes, L=512 pad, D=512 dims.
#define NB 128
#define NL 512
#define ND 512
#define TILE 16
#define ITMAX 64
#define CG_TOL 1e-4f    // on squared residual norm (direct): ||r|| <= 1e-2

// Scratch (__device__ globals; no allocations allowed)
__device__ int   g_sup_idx[NB][NL];
__device__ int   g_sup_lab[NB][NL];
__device__ int   g_qry_idx[NB][NL];
__device__ int   g_cnt[NB][4];            // [0]=ns, [1]=np, [2]=nq
__device__ float g_musum[NB][4][2][ND];   // per-part partial sums: task, pos
__device__ float g_rr[NB][2][ND];         // x_pos, x_neg  (= M^{-1} @ 1)
__device__ float g_sc[NB][4];             // mu_p.x_p, sum(mu_p), mu_n.x_n, sum(mu_n)

// ---------------------------------------------------------------------------
// Kernel 1: segmentation. batch_index is sorted -> contiguous episode ranges;
// stable split into support/query. One warp per episode.
// ---------------------------------------------------------------------------
__global__ void seg_kernel(const int* __restrict__ bidx, const int* __restrict__ isq,
                           const int* __restrict__ labels, int N) {
  int b = blockIdx.x;
  int lane = threadIdx.x;
  int start = 0, end = 0;
  if (lane == 0) {
    int lo = 0, hi = N;
    while (lo < hi) { int m = (lo + hi) >> 1; if (bidx[m] < b) lo = m + 1; else hi = m; }
    start = lo; hi = N;
    while (lo < hi) { int m = (lo + hi) >> 1; if (bidx[m] <= b) lo = m + 1; else hi = m; }
    end = lo;
  }
  start = __shfl_sync(0xffffffffu, start, 0);
  end   = __shfl_sync(0xffffffffu, end, 0);

  int sbase = 0, qbase = 0, pcnt = 0;
  for (int k0 = start; k0 < end; k0 += 32) {
    int k = k0 + lane;
    bool valid = k < end;
    int q  = valid ? isq[k]    : 0;
    int lb = valid ? labels[k] : 0;
    unsigned mq = __ballot_sync(0xffffffffu, valid && q != 0);
    unsigned ms = __ballot_sync(0xffffffffu, valid && q == 0);
    unsigned mp = __ballot_sync(0xffffffffu, valid && q == 0 && lb != 0);
    unsigned lt = (1u << lane) - 1u;
    if (valid) {
      if (q != 0) {
        int r = qbase + __popc(mq & lt);
        if (r < NL) g_qry_idx[b][r] = k;
      } else {
        int r = sbase + __popc(ms & lt);
        if (r < NL) { g_sup_idx[b][r] = k; g_sup_lab[b][r] = lb; }
      }
    }
    qbase += __popc(mq); sbase += __popc(ms); pcnt += __popc(mp);
  }
  if (lane == 0) {
    g_cnt[b][0] = min(sbase, NL);
    g_cnt[b][1] = pcnt;
    g_cnt[b][2] = min(qbase, NL);
  }
}

// ---------------------------------------------------------------------------
// Kernel 2: per-episode partial mean sums. grid (NB, 4): part p sums rows
// j = p, p+4, ...  Combined in cg_kernel prologue.
// ---------------------------------------------------------------------------
__global__ void mean_kernel(const float* __restrict__ X) {
  int b = blockIdx.x, part = blockIdx.y, d = threadIdx.x;
  int ns = g_cnt[b][0];
  float s = 0.f, sp = 0.f;
  for (int j = part; j < ns; j += 4) {
    int idx = g_sup_idx[b][j];
    int lb  = g_sup_lab[b][j];
    float v = __ldg(&X[(size_t)idx * ND + d]);
    s += v;
    if (lb) sp += v;
  }
  g_musum[b][part][0][d] = s;
  g_musum[b][part][1][d] = sp;
}

// ---------------------------------------------------------------------------
// K-wide block reduction over 512 threads, trailing barrier included.
// ---------------------------------------------------------------------------
template <int K>
__device__ __forceinline__ void redK(float* s_red, float v[K], float out[K],
                                     int lane, int w, int tid) {
  #pragma unroll
  for (int o = 16; o; o >>= 1) {
    #pragma unroll
    for (int i = 0; i < K; i++) v[i] += __shfl_down_sync(0xffffffffu, v[i], o);
  }
  if (lane == 0) {
    #pragma unroll
    for (int i = 0; i < K; i++) s_red[w * K + i] = v[i];
  }
  __syncthreads();
  if (tid < K) {
    float s = 0.f;
    #pragma unroll
    for (int w2 = 0; w2 < 16; w2++) s += s_red[w2 * K + tid];
    s_red[16 * K + tid] = s;
  }
  __syncthreads();
  #pragma unroll
  for (int i = 0; i < K; i++) out[i] = s_red[16 * K + i];
  __syncthreads();
}

// ---------------------------------------------------------------------------
// Kernel 3: fused CG for both class systems — R6-proven core:
//   * DIRECT rs = sum(r^2) and DIRECT p.q each iteration (self-stabilizing;
//     beta >= 0 by construction, alpha's denominator >= 0.1*||p||^2)
//   * 2-buffer cp.async pipeline with R6's exact 3-sync tile structure
// Safe upgrades only:
//   * two reductions per iteration instead of three: mid red2 {p.q}x2; end
//     red6 fusing {||r_new||^2}x2 with FRESH mu.r_new, so mu.p_new =
//     mu.r_new + beta*mu.p_old is a one-step identity (no drift).
//   * float4 pass-1 smem loads.
// ---------------------------------------------------------------------------
#define CG_SMEM_FLOATS (2*TILE*ND + 2*ND + 2*TILE + 2*NL + NL + 128)
#define CG_SMEM_BYTES  (CG_SMEM_FLOATS * 4)

__global__ __launch_bounds__(512, 1) void cg_kernel(const float* __restrict__ X) {
  extern __shared__ float smem[];
  float* sT    = smem;                      // [2][TILE][ND]
  float* s_pp  = sT + 2 * TILE * ND;        // [ND]
  float* s_pn  = s_pp + ND;                 // [ND]
  float* s_ep  = s_pn + ND;                 // [TILE]
  float* s_en  = s_ep + TILE;               // [TILE]
  float* s_cp  = s_en + TILE;               // [NL]
  float* s_cn  = s_cp + NL;                 // [NL]
  int*   s_idx = (int*)(s_cn + NL);         // [NL]
  float* s_red = (float*)(s_idx + NL);      // [128]

  int b = blockIdx.x, tid = threadIdx.x, lane = tid & 31, w = tid >> 5;
  int ns = g_cnt[b][0], np = g_cnt[b][1];
  float fns = (float)ns, fnp = (float)np, fnn = (float)(ns - np);
  float wt  = 0.9f / (fns - 1.f), wmt = 0.9f * fns / (fns - 1.f);
  float wp  = 0.1f / (fnp - 1.f), wmp = 0.1f * fnp / (fnp - 1.f);
  float wn  = 0.1f / (fnn - 1.f), wmn = 0.1f * fnn / (fnn - 1.f);

  for (int j = tid; j < ns; j += 512) {
    s_idx[j] = g_sup_idx[b][j];
    int lb = g_sup_lab[b][j];
    s_cp[j] = wt + (lb ? wp : 0.f);
    s_cn[j] = wt + (lb ? 0.f : wn);
  }
  // means from partial sums
  float s0 = 0.f, s1 = 0.f;
  #pragma unroll
  for (int p = 0; p < 4; p++) { s0 += g_musum[b][p][0][tid]; s1 += g_musum[b][p][1][tid]; }
  float mt  = s0 / fns;
  float mp_ = s1 / fnp;
  float mn_ = (s0 - s1) / fnn;

  // CG state (thread d owns component d); solve M x = 1 for pos & neg systems
  float xp = 0.f, xn = 0.f, rp = 1.f, rn = 1.f, pp = 1.f, pn = 1.f;
  float rsp = (float)ND, rsn = (float)ND;

  float v6[6], o6[6], v2[2], o2[2];
  #pragma unroll
  for (int i = 0; i < 6; i++) v6[i] = 0.f;
  v6[0] = mt; v6[1] = mp_; v6[2] = mn_;
  redK<6>(s_red, v6, o6, lane, w, tid);   // also fences s_idx/s_cp/s_cn
  float sigt = o6[0], sigp = o6[1], sign_ = o6[2];
  // mu.p for each system (p0 = ones)
  float mtp = sigt, mpp = sigp, mtn = sigt, mnn = sign_;

  int ntiles = (ns + TILE - 1) / TILE;
  int col4   = tid & 127;   // float4 column within row
  int rbase  = tid >> 7;    // row group 0..3

  for (int it = 0; it < ITMAX; ++it) {
    // publish search directions
    s_pp[tid] = pp; s_pn[tid] = pn;

    // prologue: async-load tile 0 into buffer 0 (R6 structure)
    {
      int tr0 = min(TILE, ns);
      #pragma unroll
      for (int s5 = 0; s5 < 4; s5++) {
        int r = rbase + s5 * 4;
        if (r < tr0) {
          int gj = s_idx[r];
          const float* src = X + (size_t)gj * ND + col4 * 4;
          unsigned dst = (unsigned)__cvta_generic_to_shared(&sT[r * ND + col4 * 4]);
          asm volatile("cp.async.cg.shared.global [%0], [%1], 16;" :: "r"(dst), "l"(src));
        }
      }
      asm volatile("cp.async.commit_group;");
    }
    __syncthreads();    // fences s_pp/s_pn publication

    // pass-1 p slices in registers (float4)
    float4 ppv[4], pnv[4];
    #pragma unroll
    for (int k = 0; k < 4; k++) {
      ppv[k] = ((const float4*)s_pp)[lane + 32 * k];
      pnv[k] = ((const float4*)s_pn)[lane + 32 * k];
    }
    float apr = 0.f, anr = 0.f;

    for (int t = 0; t < ntiles; t++) {
      int buf = t & 1;
      if (t + 1 < ntiles) {
        int j0 = (t + 1) * TILE;
        int trn = min(TILE, ns - j0);
        int bufn = (t + 1) & 1;
        #pragma unroll
        for (int s5 = 0; s5 < 4; s5++) {
          int r = rbase + s5 * 4;
          if (r < trn) {
            int gj = s_idx[j0 + r];
            const float* src = X + (size_t)gj * ND + col4 * 4;
            unsigned dst = (unsigned)__cvta_generic_to_shared(&sT[bufn * TILE * ND + r * ND + col4 * 4]);
            asm volatile("cp.async.cg.shared.global [%0], [%1], 16;" :: "r"(dst), "l"(src));
          }
        }
      }
      asm volatile("cp.async.commit_group;");   // possibly-empty group keeps wait uniform
      asm volatile("cp.async.wait_group 1;");
      __syncthreads();

      int tr = min(TILE, ns - t * TILE);
      // pass 1: warp w -> dot of row w with p (both systems), float4 loads
      if (w < tr) {
        const float4* row4 = (const float4*)(sT + ((size_t)buf * TILE + w) * ND);
        float ap = 0.f, an = 0.f;
        #pragma unroll
        for (int k = 0; k < 4; k++) {
          float4 vv = row4[lane + 32 * k];
          ap += vv.x * ppv[k].x + vv.y * ppv[k].y + vv.z * ppv[k].z + vv.w * ppv[k].w;
          an += vv.x * pnv[k].x + vv.y * pnv[k].y + vv.z * pnv[k].z + vv.w * pnv[k].w;
        }
        #pragma unroll
        for (int o = 16; o; o >>= 1) {
          ap += __shfl_down_sync(0xffffffffu, ap, o);
          an += __shfl_down_sync(0xffffffffu, an, o);
        }
        if (lane == 0) {
          int j = t * TILE + w;
          s_ep[w] = s_cp[j] * ap;
          s_en[w] = s_cn[j] * an;
        }
      }
      __syncthreads();
      // pass 2: thread d accumulates weighted rows (coalesced smem)
      const float* colp = sT + (size_t)buf * TILE * ND + tid;
      if (tr == TILE) {
        #pragma unroll
        for (int r2 = 0; r2 < TILE; r2++) {
          float vv = colp[r2 * ND];
          apr += s_ep[r2] * vv; anr += s_en[r2] * vv;
        }
      } else {
        for (int r2 = 0; r2 < tr; r2++) {
          float vv = colp[r2 * ND];
          apr += s_ep[r2] * vv; anr += s_en[r2] * vv;
        }
      }
      __syncthreads();
    }

    // q = M p (rank-1 mean corrections; mu.p exact via one-step identity)
    float qp = apr + 0.1f * pp - wmt * mtp * mt - wmp * mpp * mp_;
    float qn = anr + 0.1f * pn - wmt * mtn * mt - wmn * mnn * mn_;

    // direct p.q reduction -> alpha
    v2[0] = pp * qp; v2[1] = pn * qn;
    redK<2>(s_red, v2, o2, lane, w, tid);
    float alp = rsp / o2[0], aln = rsn / o2[1];
    xp += alp * pp;  rp -= alp * qp;
    xn += aln * pn;  rn -= aln * qn;

    // direct ||r_new||^2 + FRESH mu.r_new, all in one reduction
    v6[0] = rp * rp; v6[1] = rn * rn;
    v6[2] = mt * rp; v6[3] = mp_ * rp;
    v6[4] = mt * rn; v6[5] = mn_ * rn;
    redK<6>(s_red, v6, o6, lane, w, tid);
    float bp = o6[0] / rsp, bn = o6[1] / rsn;
    rsp = o6[0]; rsn = o6[1];
    pp = rp + bp * pp;  pn = rn + bn * pn;
    // mu.p_new = mu.r_new (fresh) + beta * mu.p_old  (exact identity)
    mtp = o6[2] + bp * mtp;  mpp = o6[3] + bp * mpp;
    mtn = o6[4] + bn * mtn;  mnn = o6[5] + bn * mnn;
    if (rsp < CG_TOL && rsn < CG_TOL) break;   // uniform across CTA
  }

  g_rr[b][0][tid] = xp;
  g_rr[b][1][tid] = xn;
  v2[0] = mp_ * xp; v2[1] = mn_ * xn;
  redK<2>(s_red, v2, o2, lane, w, tid);
  if (tid == 0) {
    g_sc[b][0] = o2[0]; g_sc[b][1] = sigp;
    g_sc[b][2] = o2[1]; g_sc[b][3] = sign_;
  }
}

// ---------------------------------------------------------------------------
// Kernel 4: outputs. maha = (q.r - mu.r) * (sum(q) - sum(mu)).
// grid (NB, 4) x 512 threads, float4 loads.
// ---------------------------------------------------------------------------
__global__ void out_kernel(const float* __restrict__ X, const float* __restrict__ log_scale,
                           float* __restrict__ out) {
  __shared__ float s_rp[ND];
  __shared__ float s_rn[ND];
  __shared__ float s_s[8];
  int b = blockIdx.x, part = blockIdx.y, tid = threadIdx.x;
  s_rp[tid] = g_rr[b][0][tid];
  s_rn[tid] = g_rr[b][1][tid];
  if (tid < 4) s_s[tid] = g_sc[b][tid];
  if (tid == 4) s_s[4] = expf(log_scale[0]);
  __syncthreads();
  int nq = g_cnt[b][2];
  int w = tid >> 5, lane = tid & 31;
  const float4* rp4 = (const float4*)s_rp;
  const float4* rn4 = (const float4*)s_rn;
  #pragma unroll
  for (int rep = 0; rep < 8; rep++) {
    int i = part * 128 + rep * 16 + w;
    if (i < nq) {
      int gj = g_qry_idx[b][i];
      const float4* q4 = (const float4*)(X + (size_t)gj * ND);
      float aqr = 0.f, aqn = 0.f, aqs = 0.f;
      #pragma unroll
      for (int k = 0; k < 4; k++) {
        float4 v = q4[lane + 32 * k];
        float4 a = rp4[lane + 32 * k];
        float4 c = rn4[lane + 32 * k];
        aqr += v.x * a.x + v.y * a.y + v.z * a.z + v.w * a.w;
        aqn += v.x * c.x + v.y * c.y + v.z * c.z + v.w * c.w;
        aqs += v.x + v.y + v.z + v.w;
      }
      #pragma unroll
      for (int o = 16; o; o >>= 1) {
        aqr += __shfl_down_sync(0xffffffffu, aqr, o);
        aqn += __shfl_down_sync(0xffffffffu, aqn, o);
        aqs += __shfl_down_sync(0xffffffffu, aqs, o);
      }
      if (lane == 0) {
        float sc = s_s[4];
        float sp = aqr - s_s[0], tp = aqs - s_s[1];
        float sn = aqn - s_s[2], tn = aqs - s_s[3];
        size_t o0 = ((size_t)b * NL + i) * 2;
        out[o0]     = sn * tn * sc;   // neg logit
        out[o0 + 1] = sp * tp * sc;   // pos logit
      }
    } else if (lane == 0) {
      size_t o0 = ((size_t)b * NL + i) * 2;
      out[o0] = 0.f; out[o0 + 1] = 0.f;
    }
  }
}

// ---------------------------------------------------------------------------
// Inputs (metadata order): graph_reprs f32[N*512], log_scale f32[1],
// labels i32[N], is_query i32[N], batch_index i32[N] (sorted).
// Output: f32[128*512*2].
// ---------------------------------------------------------------------------
extern "C" void kernel_launch(void* const* d_in, const int* in_sizes, int n_in,
                              void* d_out, int out_size) {
  const float* X      = (const float*)d_in[0];
  const float* logsc  = (const float*)d_in[1];
  const int*   labels = (const int*)d_in[2];
  const int*   isq    = (const int*)d_in[3];
  const int*   bidx   = (const int*)d_in[4];
  int N = in_sizes[2];

  cudaFuncSetAttribute(cg_kernel, cudaFuncAttributeMaxDynamicSharedMemorySize, CG_SMEM_BYTES);

  seg_kernel<<<NB, 32>>>(bidx, isq, labels, N);
  mean_kernel<<<dim3(NB, 4), ND>>>(X);
  cg_kernel<<<NB, ND, CG_SMEM_BYTES>>>(X);
  out_kernel<<<dim3(NB, 4), 512>>>(X, logsc, (float*)d_out);
}

// round 12
// speedup vs baseline: 1.3751x; 1.0527x over previous
#include <cuda_runtime.h>
#include <cstdint>
#include <math.h>

// Problem constants: B=128 episodes, L=512 pad, D=512 dims.
#define NB 128
#define NL 512
#define ND 512
#define TILE 32
#define NPART 8
#define ITMAX 64
#define CG_TOL 1e-4f    // on squared residual norm (direct): ||r|| <= 1e-2

// Scratch (__device__ globals; no allocations allowed)
__device__ int   g_sup_idx[NB][NL];
__device__ int   g_sup_lab[NB][NL];
__device__ int   g_qry_idx[NB][NL];
__device__ int   g_cnt[NB][4];              // [0]=ns, [1]=np, [2]=nq
__device__ float g_musum[NB][NPART][2][ND]; // per-part partial sums: task, pos
__device__ float g_rr[NB][2][ND];           // x_pos, x_neg  (= M^{-1} @ 1)
__device__ float g_sc[NB][4];               // mu_p.x_p, sum(mu_p), mu_n.x_n, sum(mu_n)

// ---------------------------------------------------------------------------
// Kernel 1: segmentation. batch_index is sorted -> contiguous episode ranges;
// stable split into support/query. One warp per episode.
// ---------------------------------------------------------------------------
__global__ void seg_kernel(const int* __restrict__ bidx, const int* __restrict__ isq,
                           const int* __restrict__ labels, int N) {
  int b = blockIdx.x;
  int lane = threadIdx.x;
  int start = 0, end = 0;
  if (lane == 0) {
    int lo = 0, hi = N;
    while (lo < hi) { int m = (lo + hi) >> 1; if (bidx[m] < b) lo = m + 1; else hi = m; }
    start = lo; hi = N;
    while (lo < hi) { int m = (lo + hi) >> 1; if (bidx[m] <= b) lo = m + 1; else hi = m; }
    end = lo;
  }
  start = __shfl_sync(0xffffffffu, start, 0);
  end   = __shfl_sync(0xffffffffu, end, 0);

  int sbase = 0, qbase = 0, pcnt = 0;
  for (int k0 = start; k0 < end; k0 += 32) {
    int k = k0 + lane;
    bool valid = k < end;
    int q  = valid ? isq[k]    : 0;
    int lb = valid ? labels[k] : 0;
    unsigned mq = __ballot_sync(0xffffffffu, valid && q != 0);
    unsigned ms = __ballot_sync(0xffffffffu, valid && q == 0);
    unsigned mp = __ballot_sync(0xffffffffu, valid && q == 0 && lb != 0);
    unsigned lt = (1u << lane) - 1u;
    if (valid) {
      if (q != 0) {
        int r = qbase + __popc(mq & lt);
        if (r < NL) g_qry_idx[b][r] = k;
      } else {
        int r = sbase + __popc(ms & lt);
        if (r < NL) { g_sup_idx[b][r] = k; g_sup_lab[b][r] = lb; }
      }
    }
    qbase += __popc(mq); sbase += __popc(ms); pcnt += __popc(mp);
  }
  if (lane == 0) {
    g_cnt[b][0] = min(sbase, NL);
    g_cnt[b][1] = pcnt;
    g_cnt[b][2] = min(qbase, NL);
  }
}

// ---------------------------------------------------------------------------
// Kernel 2: per-episode partial mean sums. grid (NB, NPART): part p sums rows
// j = p, p+NPART, ...  Combined in cg_kernel prologue.
// ---------------------------------------------------------------------------
__global__ void mean_kernel(const float* __restrict__ X) {
  int b = blockIdx.x, part = blockIdx.y, d = threadIdx.x;
  int ns = g_cnt[b][0];
  float s = 0.f, sp = 0.f;
  for (int j = part; j < ns; j += NPART) {
    int idx = g_sup_idx[b][j];
    int lb  = g_sup_lab[b][j];
    float v = __ldg(&X[(size_t)idx * ND + d]);
    s += v;
    if (lb) sp += v;
  }
  g_musum[b][part][0][d] = s;
  g_musum[b][part][1][d] = sp;
}

// ---------------------------------------------------------------------------
// K-wide block reduction over 512 threads, trailing barrier included.
// ---------------------------------------------------------------------------
template <int K>
__device__ __forceinline__ void redK(float* s_red, float v[K], float out[K],
                                     int lane, int w, int tid) {
  #pragma unroll
  for (int o = 16; o; o >>= 1) {
    #pragma unroll
    for (int i = 0; i < K; i++) v[i] += __shfl_down_sync(0xffffffffu, v[i], o);
  }
  if (lane == 0) {
    #pragma unroll
    for (int i = 0; i < K; i++) s_red[w * K + i] = v[i];
  }
  __syncthreads();
  if (tid < K) {
    float s = 0.f;
    #pragma unroll
    for (int w2 = 0; w2 < 16; w2++) s += s_red[w2 * K + tid];
    s_red[16 * K + tid] = s;
  }
  __syncthreads();
  #pragma unroll
  for (int i = 0; i < K; i++) out[i] = s_red[16 * K + i];
  __syncthreads();
}

// ---------------------------------------------------------------------------
// Kernel 3: fused CG for both class systems — R11-proven core, TILE 16->32:
//   * DIRECT rs = sum(r^2) and DIRECT p.q each iteration
//   * 2-buffer cp.async pipeline, SAME 3-sync-per-tile structure as R11
//     (only the row<->warp map changes: warp w does rows w and w+16)
//   * two reductions per iteration: mid red2 {p.q}x2; end red6 fusing
//     {||r_new||^2}x2 with FRESH mu.r_new (one-step mu.p identity, no drift)
// Halves the per-iteration barrier count (12 tiles -> 6).
// ---------------------------------------------------------------------------
#define CG_SMEM_FLOATS (2*TILE*ND + 2*ND + 2*TILE + 2*NL + NL + 128)
#define CG_SMEM_BYTES  (CG_SMEM_FLOATS * 4)

__global__ __launch_bounds__(512, 1) void cg_kernel(const float* __restrict__ X) {
  extern __shared__ float smem[];
  float* sT    = smem;                      // [2][TILE][ND]
  float* s_pp  = sT + 2 * TILE * ND;        // [ND]
  float* s_pn  = s_pp + ND;                 // [ND]
  float* s_ep  = s_pn + ND;                 // [TILE]
  float* s_en  = s_ep + TILE;               // [TILE]
  float* s_cp  = s_en + TILE;               // [NL]
  float* s_cn  = s_cp + NL;                 // [NL]
  int*   s_idx = (int*)(s_cn + NL);         // [NL]
  float* s_red = (float*)(s_idx + NL);      // [128]

  int b = blockIdx.x, tid = threadIdx.x, lane = tid & 31, w = tid >> 5;
  int ns = g_cnt[b][0], np = g_cnt[b][1];
  float fns = (float)ns, fnp = (float)np, fnn = (float)(ns - np);
  float wt  = 0.9f / (fns - 1.f), wmt = 0.9f * fns / (fns - 1.f);
  float wp  = 0.1f / (fnp - 1.f), wmp = 0.1f * fnp / (fnp - 1.f);
  float wn  = 0.1f / (fnn - 1.f), wmn = 0.1f * fnn / (fnn - 1.f);

  for (int j = tid; j < ns; j += 512) {
    s_idx[j] = g_sup_idx[b][j];
    int lb = g_sup_lab[b][j];
    s_cp[j] = wt + (lb ? wp : 0.f);
    s_cn[j] = wt + (lb ? 0.f : wn);
  }
  // means from partial sums
  float s0 = 0.f, s1 = 0.f;
  #pragma unroll
  for (int p = 0; p < NPART; p++) { s0 += g_musum[b][p][0][tid]; s1 += g_musum[b][p][1][tid]; }
  float mt  = s0 / fns;
  float mp_ = s1 / fnp;
  float mn_ = (s0 - s1) / fnn;

  // CG state (thread d owns component d); solve M x = 1 for pos & neg systems
  float xp = 0.f, xn = 0.f, rp = 1.f, rn = 1.f, pp = 1.f, pn = 1.f;
  float rsp = (float)ND, rsn = (float)ND;

  float v6[6], o6[6], v2[2], o2[2];
  #pragma unroll
  for (int i = 0; i < 6; i++) v6[i] = 0.f;
  v6[0] = mt; v6[1] = mp_; v6[2] = mn_;
  redK<6>(s_red, v6, o6, lane, w, tid);   // also fences s_idx/s_cp/s_cn
  float sigt = o6[0], sigp = o6[1], sign_ = o6[2];
  // mu.p for each system (p0 = ones)
  float mtp = sigt, mpp = sigp, mtn = sigt, mnn = sign_;

  int ntiles = (ns + TILE - 1) / TILE;
  int col4   = tid & 127;   // float4 column within row
  int rbase  = tid >> 7;    // row group 0..3

  for (int it = 0; it < ITMAX; ++it) {
    // publish search directions
    s_pp[tid] = pp; s_pn[tid] = pn;

    // prologue: async-load tile 0 into buffer 0
    {
      int tr0 = min(TILE, ns);
      #pragma unroll
      for (int s5 = 0; s5 < 8; s5++) {
        int r = rbase + s5 * 4;
        if (r < tr0) {
          int gj = s_idx[r];
          const float* src = X + (size_t)gj * ND + col4 * 4;
          unsigned dst = (unsigned)__cvta_generic_to_shared(&sT[r * ND + col4 * 4]);
          asm volatile("cp.async.cg.shared.global [%0], [%1], 16;" :: "r"(dst), "l"(src));
        }
      }
      asm volatile("cp.async.commit_group;");
    }
    __syncthreads();    // fences s_pp/s_pn publication

    // pass-1 p slices in registers (float4)
    float4 ppv[4], pnv[4];
    #pragma unroll
    for (int k = 0; k < 4; k++) {
      ppv[k] = ((const float4*)s_pp)[lane + 32 * k];
      pnv[k] = ((const float4*)s_pn)[lane + 32 * k];
    }
    float apr = 0.f, anr = 0.f;

    for (int t = 0; t < ntiles; t++) {
      int buf = t & 1;
      if (t + 1 < ntiles) {
        int j0 = (t + 1) * TILE;
        int trn = min(TILE, ns - j0);
        int bufn = (t + 1) & 1;
        #pragma unroll
        for (int s5 = 0; s5 < 8; s5++) {
          int r = rbase + s5 * 4;
          if (r < trn) {
            int gj = s_idx[j0 + r];
            const float* src = X + (size_t)gj * ND + col4 * 4;
            unsigned dst = (unsigned)__cvta_generic_to_shared(&sT[bufn * TILE * ND + r * ND + col4 * 4]);
            asm volatile("cp.async.cg.shared.global [%0], [%1], 16;" :: "r"(dst), "l"(src));
          }
        }
      }
      asm volatile("cp.async.commit_group;");   // possibly-empty group keeps wait uniform
      asm volatile("cp.async.wait_group 1;");
      __syncthreads();

      int tr = min(TILE, ns - t * TILE);
      // pass 1: warp w -> rows w and w+16 dotted with p (both systems)
      {
        float ap0 = 0.f, an0 = 0.f, ap1 = 0.f, an1 = 0.f;
        if (w < tr) {
          const float4* row4 = (const float4*)(sT + ((size_t)buf * TILE + w) * ND);
          #pragma unroll
          for (int k = 0; k < 4; k++) {
            float4 vv = row4[lane + 32 * k];
            ap0 += vv.x * ppv[k].x + vv.y * ppv[k].y + vv.z * ppv[k].z + vv.w * ppv[k].w;
            an0 += vv.x * pnv[k].x + vv.y * pnv[k].y + vv.z * pnv[k].z + vv.w * pnv[k].w;
          }
        }
        if (w + 16 < tr) {
          const float4* row4 = (const float4*)(sT + ((size_t)buf * TILE + w + 16) * ND);
          #pragma unroll
          for (int k = 0; k < 4; k++) {
            float4 vv = row4[lane + 32 * k];
            ap1 += vv.x * ppv[k].x + vv.y * ppv[k].y + vv.z * ppv[k].z + vv.w * ppv[k].w;
            an1 += vv.x * pnv[k].x + vv.y * pnv[k].y + vv.z * pnv[k].z + vv.w * pnv[k].w;
          }
        }
        #pragma unroll
        for (int o = 16; o; o >>= 1) {
          ap0 += __shfl_down_sync(0xffffffffu, ap0, o);
          an0 += __shfl_down_sync(0xffffffffu, an0, o);
          ap1 += __shfl_down_sync(0xffffffffu, ap1, o);
          an1 += __shfl_down_sync(0xffffffffu, an1, o);
        }
        if (lane == 0) {
          int j = t * TILE + w;
          if (w < tr)      { s_ep[w]      = s_cp[j]      * ap0;  s_en[w]      = s_cn[j]      * an0; }
          if (w + 16 < tr) { s_ep[w + 16] = s_cp[j + 16] * ap1;  s_en[w + 16] = s_cn[j + 16] * an1; }
        }
      }
      __syncthreads();
      // pass 2: thread d accumulates weighted rows (coalesced smem)
      const float* colp = sT + (size_t)buf * TILE * ND + tid;
      if (tr == TILE) {
        #pragma unroll
        for (int r2 = 0; r2 < TILE; r2++) {
          float vv = colp[r2 * ND];
          apr += s_ep[r2] * vv; anr += s_en[r2] * vv;
        }
      } else {
        for (int r2 = 0; r2 < tr; r2++) {
          float vv = colp[r2 * ND];
          apr += s_ep[r2] * vv; anr += s_en[r2] * vv;
        }
      }
      __syncthreads();
    }

    // q = M p (rank-1 mean corrections; mu.p exact via one-step identity)
    float qp = apr + 0.1f * pp - wmt * mtp * mt - wmp * mpp * mp_;
    float qn = anr + 0.1f * pn - wmt * mtn * mt - wmn * mnn * mn_;

    // direct p.q reduction -> alpha
    v2[0] = pp * qp; v2[1] = pn * qn;
    redK<2>(s_red, v2, o2, lane, w, tid);
    float alp = rsp / o2[0], aln = rsn / o2[1];
    xp += alp * pp;  rp -= alp * qp;
    xn += aln * pn;  rn -= aln * qn;

    // direct ||r_new||^2 + FRESH mu.r_new, all in one reduction
    v6[0] = rp * rp; v6[1] = rn * rn;
    v6[2] = mt * rp; v6[3] = mp_ * rp;
    v6[4] = mt * rn; v6[5] = mn_ * rn;
    redK<6>(s_red, v6, o6, lane, w, tid);
    float bp = o6[0] / rsp, bn = o6[1] / rsn;
    rsp = o6[0]; rsn = o6[1];
    pp = rp + bp * pp;  pn = rn + bn * pn;
    // mu.p_new = mu.r_new (fresh) + beta * mu.p_old  (exact identity)
    mtp = o6[2] + bp * mtp;  mpp = o6[3] + bp * mpp;
    mtn = o6[4] + bn * mtn;  mnn = o6[5] + bn * mnn;
    if (rsp < CG_TOL && rsn < CG_TOL) break;   // uniform across CTA
  }

  g_rr[b][0][tid] = xp;
  g_rr[b][1][tid] = xn;
  v2[0] = mp_ * xp; v2[1] = mn_ * xn;
  redK<2>(s_red, v2, o2, lane, w, tid);
  if (tid == 0) {
    g_sc[b][0] = o2[0]; g_sc[b][1] = sigp;
    g_sc[b][2] = o2[1]; g_sc[b][3] = sign_;
  }
}

// ---------------------------------------------------------------------------
// Kernel 4: outputs. maha = (q.r - mu.r) * (sum(q) - sum(mu)).
// grid (NB, 4) x 512 threads, float4 loads.
// ---------------------------------------------------------------------------
__global__ void out_kernel(const float* __restrict__ X, const float* __restrict__ log_scale,
                           float* __restrict__ out) {
  __shared__ float s_rp[ND];
  __shared__ float s_rn[ND];
  __shared__ float s_s[8];
  int b = blockIdx.x, part = blockIdx.y, tid = threadIdx.x;
  s_rp[tid] = g_rr[b][0][tid];
  s_rn[tid] = g_rr[b][1][tid];
  if (tid < 4) s_s[tid] = g_sc[b][tid];
  if (tid == 4) s_s[4] = expf(log_scale[0]);
  __syncthreads();
  int nq = g_cnt[b][2];
  int w = tid >> 5, lane = tid & 31;
  const float4* rp4 = (const float4*)s_rp;
  const float4* rn4 = (const float4*)s_rn;
  #pragma unroll
  for (int rep = 0; rep < 8; rep++) {
    int i = part * 128 + rep * 16 + w;
    if (i < nq) {
      int gj = g_qry_idx[b][i];
      const float4* q4 = (const float4*)(X + (size_t)gj * ND);
      float aqr = 0.f, aqn = 0.f, aqs = 0.f;
      #pragma unroll
      for (int k = 0; k < 4; k++) {
        float4 v = q4[lane + 32 * k];
        float4 a = rp4[lane + 32 * k];
        float4 c = rn4[lane + 32 * k];
        aqr += v.x * a.x + v.y * a.y + v.z * a.z + v.w * a.w;
        aqn += v.x * c.x + v.y * c.y + v.z * c.z + v.w * c.w;
        aqs += v.x + v.y + v.z + v.w;
      }
      #pragma unroll
      for (int o = 16; o; o >>= 1) {
        aqr += __shfl_down_sync(0xffffffffu, aqr, o);
        aqn += __shfl_down_sync(0xffffffffu, aqn, o);
        aqs += __shfl_down_sync(0xffffffffu, aqs, o);
      }
      if (lane == 0) {
        float sc = s_s[4];
        float sp = aqr - s_s[0], tp = aqs - s_s[1];
        float sn = aqn - s_s[2], tn = aqs - s_s[3];
        size_t o0 = ((size_t)b * NL + i) * 2;
        out[o0]     = sn * tn * sc;   // neg logit
        out[o0 + 1] = sp * tp * sc;   // pos logit
      }
    } else if (lane == 0) {
      size_t o0 = ((size_t)b * NL + i) * 2;
      out[o0] = 0.f; out[o0 + 1] = 0.f;
    }
  }
}

// ---------------------------------------------------------------------------
// Inputs (metadata order): graph_reprs f32[N*512], log_scale f32[1],
// labels i32[N], is_query i32[N], batch_index i32[N] (sorted).
// Output: f32[128*512*2].
// ---------------------------------------------------------------------------
extern "C" void kernel_launch(void* const* d_in, const int* in_sizes, int n_in,
                              void* d_out, int out_size) {
  const float* X      = (const float*)d_in[0];
  const float* logsc  = (const float*)d_in[1];
  const int*   labels = (const int*)d_in[2];
  const int*   isq    = (const int*)d_in[3];
  const int*   bidx   = (const int*)d_in[4];
  int N = in_sizes[2];

  cudaFuncSetAttribute(cg_kernel, cudaFuncAttributeMaxDynamicSharedMemorySize, CG_SMEM_BYTES);

  seg_kernel<<<NB, 32>>>(bidx, isq, labels, N);
  mean_kernel<<<dim3(NB, NPART), ND>>>(X);
  cg_kernel<<<NB, ND, CG_SMEM_BYTES>>>(X);
  out_kernel<<<dim3(NB, 4), 512>>>(X, logsc, (float*)d_out);
}

// round 13
// speedup vs baseline: 2.1809x; 1.5860x over previous
#include <cuda_runtime.h>
#include <cstdint>
#include <math.h>

// Problem constants: B=128 episodes, L=512 pad, D=512 dims.
#define NB 128
#define NL 512
#define ND 512
#define NPART 8
#define ITMAX 64
#define CG_TOL 1e-3f    // on squared residual norm (direct): ||r|| <= ~0.032

// Scratch (__device__ globals; no allocations allowed)
__device__ int   g_sup_idx[NB][NL];
__device__ int   g_sup_lab[NB][NL];
__device__ int   g_qry_idx[NB][NL];
__device__ int   g_cnt[NB][4];              // [0]=ns, [1]=np, [2]=nq
__device__ float g_musum[NB][NPART][2][ND]; // per-part partial sums: task, pos
__device__ float g_rr[NB][2][ND];           // x_pos, x_neg  (= M^{-1} @ 1)
__device__ float g_sc[NB][4];               // mu_p.x_p, sum(mu_p), mu_n.x_n, sum(mu_n)

// ---------------------------------------------------------------------------
// Kernel 1: segmentation. batch_index is sorted -> contiguous episode ranges;
// stable split into support/query. One warp per episode.
// ---------------------------------------------------------------------------
__global__ void seg_kernel(const int* __restrict__ bidx, const int* __restrict__ isq,
                           const int* __restrict__ labels, int N) {
  int b = blockIdx.x;
  int lane = threadIdx.x;
  int start = 0, end = 0;
  if (lane == 0) {
    int lo = 0, hi = N;
    while (lo < hi) { int m = (lo + hi) >> 1; if (bidx[m] < b) lo = m + 1; else hi = m; }
    start = lo; hi = N;
    while (lo < hi) { int m = (lo + hi) >> 1; if (bidx[m] <= b) lo = m + 1; else hi = m; }
    end = lo;
  }
  start = __shfl_sync(0xffffffffu, start, 0);
  end   = __shfl_sync(0xffffffffu, end, 0);

  int sbase = 0, qbase = 0, pcnt = 0;
  for (int k0 = start; k0 < end; k0 += 32) {
    int k = k0 + lane;
    bool valid = k < end;
    int q  = valid ? isq[k]    : 0;
    int lb = valid ? labels[k] : 0;
    unsigned mq = __ballot_sync(0xffffffffu, valid && q != 0);
    unsigned ms = __ballot_sync(0xffffffffu, valid && q == 0);
    unsigned mp = __ballot_sync(0xffffffffu, valid && q == 0 && lb != 0);
    unsigned lt = (1u << lane) - 1u;
    if (valid) {
      if (q != 0) {
        int r = qbase + __popc(mq & lt);
        if (r < NL) g_qry_idx[b][r] = k;
      } else {
        int r = sbase + __popc(ms & lt);
        if (r < NL) { g_sup_idx[b][r] = k; g_sup_lab[b][r] = lb; }
      }
    }
    qbase += __popc(mq); sbase += __popc(ms); pcnt += __popc(mp);
  }
  if (lane == 0) {
    g_cnt[b][0] = min(sbase, NL);
    g_cnt[b][1] = pcnt;
    g_cnt[b][2] = min(qbase, NL);
  }
}

// ---------------------------------------------------------------------------
// Kernel 2: per-episode partial mean sums. grid (NB, NPART).
// ---------------------------------------------------------------------------
__global__ void mean_kernel(const float* __restrict__ X) {
  int b = blockIdx.x, part = blockIdx.y, d = threadIdx.x;
  int ns = g_cnt[b][0];
  float s = 0.f, sp = 0.f;
  for (int j = part; j < ns; j += NPART) {
    int idx = g_sup_idx[b][j];
    int lb  = g_sup_lab[b][j];
    float v = __ldg(&X[(size_t)idx * ND + d]);
    s += v;
    if (lb) sp += v;
  }
  g_musum[b][part][0][d] = s;
  g_musum[b][part][1][d] = sp;
}

// ---------------------------------------------------------------------------
// K-wide block reduction over 512 threads, trailing barrier included.
// ---------------------------------------------------------------------------
template <int K>
__device__ __forceinline__ void redK(float* s_red, float v[K], float out[K],
                                     int lane, int w, int tid) {
  #pragma unroll
  for (int o = 16; o; o >>= 1) {
    #pragma unroll
    for (int i = 0; i < K; i++) v[i] += __shfl_down_sync(0xffffffffu, v[i], o);
  }
  if (lane == 0) {
    #pragma unroll
    for (int i = 0; i < K; i++) s_red[w * K + i] = v[i];
  }
  __syncthreads();
  if (tid < K) {
    float s = 0.f;
    #pragma unroll
    for (int w2 = 0; w2 < 16; w2++) s += s_red[w2 * K + tid];
    s_red[16 * K + tid] = s;
  }
  __syncthreads();
  #pragma unroll
  for (int i = 0; i < K; i++) out[i] = s_red[16 * K + i];
  __syncthreads();
}

// ---------------------------------------------------------------------------
// Kernel 3: fused CG, register-resident matvec.
// CG scalar math IDENTICAL to R11/R12 (direct rs, direct p.q, fresh mu.r).
// Matvec dataflow: warp w owns rows j = w mod 16. Per row: LDG 4xfloat4 ->
// dot vs register p-slices -> warp shfl-reduce -> broadcast e = c*(x.p)
// inside the warp (no smem) -> accumulate e*x into per-thread partial-Ap
// registers from the SAME registers. X touched once per iteration; no smem
// staging, no per-tile barriers (LDGs pipeline freely across rows).
// One cross-warp partial reduction (64KB smem) per iteration.
// ---------------------------------------------------------------------------
#define CG_SMEM_FLOATS (2*ND + 2*NL + NL + 16*2*ND + 128)
#define CG_SMEM_BYTES  (CG_SMEM_FLOATS * 4)

__global__ __launch_bounds__(512, 1) void cg_kernel(const float* __restrict__ X) {
  extern __shared__ float smem[];
  float* s_pp  = smem;                  // [ND]
  float* s_pn  = s_pp + ND;             // [ND]
  float* s_cp  = s_pn + ND;             // [NL]
  float* s_cn  = s_cp + NL;             // [NL]
  int*   s_idx = (int*)(s_cn + NL);     // [NL]
  float* s_part= (float*)(s_idx + NL);  // [16][2][ND]
  float* s_red = s_part + 16 * 2 * ND;  // [128]

  int b = blockIdx.x, tid = threadIdx.x, lane = tid & 31, w = tid >> 5;
  int ns = g_cnt[b][0], np = g_cnt[b][1];
  float fns = (float)ns, fnp = (float)np, fnn = (float)(ns - np);
  float wt  = 0.9f / (fns - 1.f), wmt = 0.9f * fns / (fns - 1.f);
  float wp  = 0.1f / (fnp - 1.f), wmp = 0.1f * fnp / (fnp - 1.f);
  float wn  = 0.1f / (fnn - 1.f), wmn = 0.1f * fnn / (fnn - 1.f);

  for (int j = tid; j < ns; j += 512) {
    s_idx[j] = g_sup_idx[b][j];
    int lb = g_sup_lab[b][j];
    s_cp[j] = wt + (lb ? wp : 0.f);
    s_cn[j] = wt + (lb ? 0.f : wn);
  }
  // means from partial sums
  float s0 = 0.f, s1 = 0.f;
  #pragma unroll
  for (int p = 0; p < NPART; p++) { s0 += g_musum[b][p][0][tid]; s1 += g_musum[b][p][1][tid]; }
  float mt  = s0 / fns;
  float mp_ = s1 / fnp;
  float mn_ = (s0 - s1) / fnn;

  // CG state (thread d owns component d); solve M x = 1 for pos & neg systems
  float xp = 0.f, xn = 0.f, rp = 1.f, rn = 1.f, pp = 1.f, pn = 1.f;
  float rsp = (float)ND, rsn = (float)ND;

  float v6[6], o6[6], v2[2], o2[2];
  #pragma unroll
  for (int i = 0; i < 6; i++) v6[i] = 0.f;
  v6[0] = mt; v6[1] = mp_; v6[2] = mn_;
  redK<6>(s_red, v6, o6, lane, w, tid);   // also fences s_idx/s_cp/s_cn
  float sigt = o6[0], sigp = o6[1], sign_ = o6[2];
  // mu.p for each system (p0 = ones)
  float mtp = sigt, mpp = sigp, mtn = sigt, mnn = sign_;

  int ntiles = (ns + 15) >> 4;   // 16 rows per "tile" (1 row per warp)

  for (int it = 0; it < ITMAX; ++it) {
    // publish search directions
    s_pp[tid] = pp; s_pn[tid] = pn;
    __syncthreads();

    // p slices in registers (float4); thread's columns are 4*(lane+32k)+0..3
    float4 ppv[4], pnv[4];
    #pragma unroll
    for (int k = 0; k < 4; k++) {
      ppv[k] = ((const float4*)s_pp)[lane + 32 * k];
      pnv[k] = ((const float4*)s_pn)[lane + 32 * k];
    }

    // per-thread partial Ap accumulators over this thread's 16 columns
    float4 accp[4], accn[4];
    #pragma unroll
    for (int k = 0; k < 4; k++) {
      accp[k] = make_float4(0.f, 0.f, 0.f, 0.f);
      accn[k] = make_float4(0.f, 0.f, 0.f, 0.f);
    }

    // barrier-free row loop: warp w handles rows w, w+16, w+32, ...
    for (int t = 0; t < ntiles; t++) {
      int j = t * 16 + w;
      if (j < ns) {                       // warp-uniform branch
        const float4* row4 = (const float4*)(X + (size_t)s_idx[j] * ND);
        float4 xv[4];
        #pragma unroll
        for (int k = 0; k < 4; k++) xv[k] = __ldg(&row4[lane + 32 * k]);
        float ap = 0.f, an = 0.f;
        #pragma unroll
        for (int k = 0; k < 4; k++) {
          ap += xv[k].x * ppv[k].x + xv[k].y * ppv[k].y + xv[k].z * ppv[k].z + xv[k].w * ppv[k].w;
          an += xv[k].x * pnv[k].x + xv[k].y * pnv[k].y + xv[k].z * pnv[k].z + xv[k].w * pnv[k].w;
        }
        #pragma unroll
        for (int o = 16; o; o >>= 1) {
          ap += __shfl_down_sync(0xffffffffu, ap, o);
          an += __shfl_down_sync(0xffffffffu, an, o);
        }
        ap = __shfl_sync(0xffffffffu, ap, 0);
        an = __shfl_sync(0xffffffffu, an, 0);
        float ep = s_cp[j] * ap;          // broadcast smem read
        float en = s_cn[j] * an;
        #pragma unroll
        for (int k = 0; k < 4; k++) {
          accp[k].x += ep * xv[k].x; accp[k].y += ep * xv[k].y;
          accp[k].z += ep * xv[k].z; accp[k].w += ep * xv[k].w;
          accn[k].x += en * xv[k].x; accn[k].y += en * xv[k].y;
          accn[k].z += en * xv[k].z; accn[k].w += en * xv[k].w;
        }
      }
    }

    // cross-warp partial reduction (once per iteration).
    // Safe to write without a leading barrier: previous iteration's s_part
    // reads precede redK<2>'s barriers.
    #pragma unroll
    for (int k = 0; k < 4; k++) {
      ((float4*)(s_part + (size_t)(w * 2 + 0) * ND))[lane + 32 * k] = accp[k];
      ((float4*)(s_part + (size_t)(w * 2 + 1) * ND))[lane + 32 * k] = accn[k];
    }
    __syncthreads();
    float apr = 0.f, anr = 0.f;
    #pragma unroll
    for (int w2 = 0; w2 < 16; w2++) {
      apr += s_part[(size_t)(w2 * 2 + 0) * ND + tid];
      anr += s_part[(size_t)(w2 * 2 + 1) * ND + tid];
    }

    // q = M p (rank-1 mean corrections; mu.p exact via one-step identity)
    float qp = apr + 0.1f * pp - wmt * mtp * mt - wmp * mpp * mp_;
    float qn = anr + 0.1f * pn - wmt * mtn * mt - wmn * mnn * mn_;

    // direct p.q reduction -> alpha
    v2[0] = pp * qp; v2[1] = pn * qn;
    redK<2>(s_red, v2, o2, lane, w, tid);
    float alp = rsp / o2[0], aln = rsn / o2[1];
    xp += alp * pp;  rp -= alp * qp;
    xn += aln * pn;  rn -= aln * qn;

    // direct ||r_new||^2 + FRESH mu.r_new, all in one reduction
    v6[0] = rp * rp; v6[1] = rn * rn;
    v6[2] = mt * rp; v6[3] = mp_ * rp;
    v6[4] = mt * rn; v6[5] = mn_ * rn;
    redK<6>(s_red, v6, o6, lane, w, tid);
    float bp = o6[0] / rsp, bn = o6[1] / rsn;
    rsp = o6[0]; rsn = o6[1];
    pp = rp + bp * pp;  pn = rn + bn * pn;
    // mu.p_new = mu.r_new (fresh) + beta * mu.p_old  (exact identity)
    mtp = o6[2] + bp * mtp;  mpp = o6[3] + bp * mpp;
    mtn = o6[4] + bn * mtn;  mnn = o6[5] + bn * mnn;
    if (rsp < CG_TOL && rsn < CG_TOL) break;   // uniform across CTA
  }

  g_rr[b][0][tid] = xp;
  g_rr[b][1][tid] = xn;
  v2[0] = mp_ * xp; v2[1] = mn_ * xn;
  redK<2>(s_red, v2, o2, lane, w, tid);
  if (tid == 0) {
    g_sc[b][0] = o2[0]; g_sc[b][1] = sigp;
    g_sc[b][2] = o2[1]; g_sc[b][3] = sign_;
  }
}

// ---------------------------------------------------------------------------
// Kernel 4: outputs. maha = (q.r - mu.r) * (sum(q) - sum(mu)).
// grid (NB, 4) x 512 threads, float4 loads.
// ---------------------------------------------------------------------------
__global__ void out_kernel(const float* __restrict__ X, const float* __restrict__ log_scale,
                           float* __restrict__ out) {
  __shared__ float s_rp[ND];
  __shared__ float s_rn[ND];
  __shared__ float s_s[8];
  int b = blockIdx.x, part = blockIdx.y, tid = threadIdx.x;
  s_rp[tid] = g_rr[b][0][tid];
  s_rn[tid] = g_rr[b][1][tid];
  if (tid < 4) s_s[tid] = g_sc[b][tid];
  if (tid == 4) s_s[4] = expf(log_scale[0]);
  __syncthreads();
  int nq = g_cnt[b][2];
  int w = tid >> 5, lane = tid & 31;
  const float4* rp4 = (const float4*)s_rp;
  const float4* rn4 = (const float4*)s_rn;
  #pragma unroll
  for (int rep = 0; rep < 8; rep++) {
    int i = part * 128 + rep * 16 + w;
    if (i < nq) {
      int gj = g_qry_idx[b][i];
      const float4* q4 = (const float4*)(X + (size_t)gj * ND);
      float aqr = 0.f, aqn = 0.f, aqs = 0.f;
      #pragma unroll
      for (int k = 0; k < 4; k++) {
        float4 v = q4[lane + 32 * k];
        float4 a = rp4[lane + 32 * k];
        float4 c = rn4[lane + 32 * k];
        aqr += v.x * a.x + v.y * a.y + v.z * a.z + v.w * a.w;
        aqn += v.x * c.x + v.y * c.y + v.z * c.z + v.w * c.w;
        aqs += v.x + v.y + v.z + v.w;
      }
      #pragma unroll
      for (int o = 16; o; o >>= 1) {
        aqr += __shfl_down_sync(0xffffffffu, aqr, o);
        aqn += __shfl_down_sync(0xffffffffu, aqn, o);
        aqs += __shfl_down_sync(0xffffffffu, aqs, o);
      }
      if (lane == 0) {
        float sc = s_s[4];
        float sp = aqr - s_s[0], tp = aqs - s_s[1];
        float sn = aqn - s_s[2], tn = aqs - s_s[3];
        size_t o0 = ((size_t)b * NL + i) * 2;
        out[o0]     = sn * tn * sc;   // neg logit
        out[o0 + 1] = sp * tp * sc;   // pos logit
      }
    } else if (lane == 0) {
      size_t o0 = ((size_t)b * NL + i) * 2;
      out[o0] = 0.f; out[o0 + 1] = 0.f;
    }
  }
}

// ---------------------------------------------------------------------------
// Inputs (metadata order): graph_reprs f32[N*512], log_scale f32[1],
// labels i32[N], is_query i32[N], batch_index i32[N] (sorted).
// Output: f32[128*512*2].
// ---------------------------------------------------------------------------
extern "C" void kernel_launch(void* const* d_in, const int* in_sizes, int n_in,
                              void* d_out, int out_size) {
  const float* X      = (const float*)d_in[0];
  const float* logsc  = (const float*)d_in[1];
  const int*   labels = (const int*)d_in[2];
  const int*   isq    = (const int*)d_in[3];
  const int*   bidx   = (const int*)d_in[4];
  int N = in_sizes[2];

  cudaFuncSetAttribute(cg_kernel, cudaFuncAttributeMaxDynamicSharedMemorySize, CG_SMEM_BYTES);

  seg_kernel<<<NB, 32>>>(bidx, isq, labels, N);
  mean_kernel<<<dim3(NB, NPART), ND>>>(X);
  cg_kernel<<<NB, ND, CG_SMEM_BYTES>>>(X);
  out_kernel<<<dim3(NB, 4), 512>>>(X, logsc, (float*)d_out);
}

// round 14
// speedup vs baseline: 2.3738x; 1.0884x over previous
#include <cuda_runtime.h>
#include <cstdint>
#include <math.h>

// Problem constants: B=128 episodes, L=512 pad, D=512 dims.
#define NB 128
#define NL 512
#define ND 512
#define NPART 8
#define ITMAX 64
#define CROWS 88        // support rows cached persistently in smem
#define CG_TOL 1e-2f    // on squared residual norm: ||r|| <= ~0.1 (rel_err ~ 2e-4)

// Scratch (__device__ globals; no allocations allowed)
__device__ int   g_sup_idx[NB][NL];
__device__ int   g_sup_lab[NB][NL];
__device__ int   g_qry_idx[NB][NL];
__device__ int   g_cnt[NB][4];              // [0]=ns, [1]=np, [2]=nq
__device__ float g_musum[NB][NPART][2][ND]; // per-part partial sums: task, pos
__device__ float g_rr[NB][2][ND];           // x_pos, x_neg  (= M^{-1} @ 1)
__device__ float g_sc[NB][4];               // mu_p.x_p, sum(mu_p), mu_n.x_n, sum(mu_n)

// ---------------------------------------------------------------------------
// Kernel 1: segmentation. batch_index is sorted -> contiguous episode ranges;
// stable split into support/query. One warp per episode.
// ---------------------------------------------------------------------------
__global__ void seg_kernel(const int* __restrict__ bidx, const int* __restrict__ isq,
                           const int* __restrict__ labels, int N) {
  int b = blockIdx.x;
  int lane = threadIdx.x;
  int start = 0, end = 0;
  if (lane == 0) {
    int lo = 0, hi = N;
    while (lo < hi) { int m = (lo + hi) >> 1; if (bidx[m] < b) lo = m + 1; else hi = m; }
    start = lo; hi = N;
    while (lo < hi) { int m = (lo + hi) >> 1; if (bidx[m] <= b) lo = m + 1; else hi = m; }
    end = lo;
  }
  start = __shfl_sync(0xffffffffu, start, 0);
  end   = __shfl_sync(0xffffffffu, end, 0);

  int sbase = 0, qbase = 0, pcnt = 0;
  for (int k0 = start; k0 < end; k0 += 32) {
    int k = k0 + lane;
    bool valid = k < end;
    int q  = valid ? isq[k]    : 0;
    int lb = valid ? labels[k] : 0;
    unsigned mq = __ballot_sync(0xffffffffu, valid && q != 0);
    unsigned ms = __ballot_sync(0xffffffffu, valid && q == 0);
    unsigned mp = __ballot_sync(0xffffffffu, valid && q == 0 && lb != 0);
    unsigned lt = (1u << lane) - 1u;
    if (valid) {
      if (q != 0) {
        int r = qbase + __popc(mq & lt);
        if (r < NL) g_qry_idx[b][r] = k;
      } else {
        int r = sbase + __popc(ms & lt);
        if (r < NL) { g_sup_idx[b][r] = k; g_sup_lab[b][r] = lb; }
      }
    }
    qbase += __popc(mq); sbase += __popc(ms); pcnt += __popc(mp);
  }
  if (lane == 0) {
    g_cnt[b][0] = min(sbase, NL);
    g_cnt[b][1] = pcnt;
    g_cnt[b][2] = min(qbase, NL);
  }
}

// ---------------------------------------------------------------------------
// Kernel 2: per-episode partial mean sums. grid (NB, NPART).
// ---------------------------------------------------------------------------
__global__ void mean_kernel(const float* __restrict__ X) {
  int b = blockIdx.x, part = blockIdx.y, d = threadIdx.x;
  int ns = g_cnt[b][0];
  float s = 0.f, sp = 0.f;
  for (int j = part; j < ns; j += NPART) {
    int idx = g_sup_idx[b][j];
    int lb  = g_sup_lab[b][j];
    float v = __ldg(&X[(size_t)idx * ND + d]);
    s += v;
    if (lb) sp += v;
  }
  g_musum[b][part][0][d] = s;
  g_musum[b][part][1][d] = sp;
}

// ---------------------------------------------------------------------------
// K-wide block reduction over 512 threads, trailing barrier included.
// ---------------------------------------------------------------------------
template <int K>
__device__ __forceinline__ void redK(float* s_red, float v[K], float out[K],
                                     int lane, int w, int tid) {
  #pragma unroll
  for (int o = 16; o; o >>= 1) {
    #pragma unroll
    for (int i = 0; i < K; i++) v[i] += __shfl_down_sync(0xffffffffu, v[i], o);
  }
  if (lane == 0) {
    #pragma unroll
    for (int i = 0; i < K; i++) s_red[w * K + i] = v[i];
  }
  __syncthreads();
  if (tid < K) {
    float s = 0.f;
    #pragma unroll
    for (int w2 = 0; w2 < 16; w2++) s += s_red[w2 * K + tid];
    s_red[16 * K + tid] = s;
  }
  __syncthreads();
  #pragma unroll
  for (int i = 0; i < K; i++) out[i] = s_red[16 * K + i];
  __syncthreads();
}

// ---------------------------------------------------------------------------
// Kernel 3: fused CG, register-resident matvec + persistent smem row cache.
// CG scalar math IDENTICAL to R11-R13 (direct rs, direct p.q, fresh mu.r).
// Rows j < CROWS are read from a persistent smem cache (filled once before
// the loop); the rest stream from L2. Cross-warp partial reduction done in
// TWO rounds (p then n) through a 16x512 buffer to free smem for the cache.
// ---------------------------------------------------------------------------
#define CG_SMEM_FLOATS (2*ND + 2*NL + NL + 16*ND + 128 + CROWS*ND)
#define CG_SMEM_BYTES  (CG_SMEM_FLOATS * 4)

__global__ __launch_bounds__(512, 1) void cg_kernel(const float* __restrict__ X) {
  extern __shared__ float smem[];
  float* s_pp  = smem;                  // [ND]
  float* s_pn  = s_pp + ND;             // [ND]
  float* s_cp  = s_pn + ND;             // [NL]
  float* s_cn  = s_cp + NL;             // [NL]
  int*   s_idx = (int*)(s_cn + NL);     // [NL]
  float* s_part= (float*)(s_idx + NL);  // [16][ND]
  float* s_red = s_part + 16 * ND;      // [128]
  float* s_cache = s_red + 128;         // [CROWS][ND]

  int b = blockIdx.x, tid = threadIdx.x, lane = tid & 31, w = tid >> 5;
  int ns = g_cnt[b][0], np = g_cnt[b][1];
  float fns = (float)ns, fnp = (float)np, fnn = (float)(ns - np);
  float wt  = 0.9f / (fns - 1.f), wmt = 0.9f * fns / (fns - 1.f);
  float wp  = 0.1f / (fnp - 1.f), wmp = 0.1f * fnp / (fnp - 1.f);
  float wn  = 0.1f / (fnn - 1.f), wmn = 0.1f * fnn / (fnn - 1.f);

  for (int j = tid; j < ns; j += 512) {
    s_idx[j] = g_sup_idx[b][j];
    int lb = g_sup_lab[b][j];
    s_cp[j] = wt + (lb ? wp : 0.f);
    s_cn[j] = wt + (lb ? 0.f : wn);
  }
  // fill persistent row cache with cp.async (rows 0..min(ns,CROWS)-1)
  {
    int cr = min(ns, CROWS);
    for (int i4 = tid; i4 < cr * 128; i4 += 512) {
      int r = i4 >> 7, c = i4 & 127;
      int gj = g_sup_idx[b][r];
      const float* src = X + (size_t)gj * ND + c * 4;
      unsigned dst = (unsigned)__cvta_generic_to_shared(&s_cache[(size_t)r * ND + c * 4]);
      asm volatile("cp.async.cg.shared.global [%0], [%1], 16;" :: "r"(dst), "l"(src));
    }
    asm volatile("cp.async.commit_group;");
    asm volatile("cp.async.wait_group 0;");
  }
  // means from partial sums
  float s0 = 0.f, s1 = 0.f;
  #pragma unroll
  for (int p = 0; p < NPART; p++) { s0 += g_musum[b][p][0][tid]; s1 += g_musum[b][p][1][tid]; }
  float mt  = s0 / fns;
  float mp_ = s1 / fnp;
  float mn_ = (s0 - s1) / fnn;

  // CG state (thread d owns component d); solve M x = 1 for pos & neg systems
  float xp = 0.f, xn = 0.f, rp = 1.f, rn = 1.f, pp = 1.f, pn = 1.f;
  float rsp = (float)ND, rsn = (float)ND;

  float v6[6], o6[6], v2[2], o2[2];
  #pragma unroll
  for (int i = 0; i < 6; i++) v6[i] = 0.f;
  v6[0] = mt; v6[1] = mp_; v6[2] = mn_;
  redK<6>(s_red, v6, o6, lane, w, tid);   // barriers fence s_idx/s_cp/s_cn/cache
  float sigt = o6[0], sigp = o6[1], sign_ = o6[2];
  // mu.p for each system (p0 = ones)
  float mtp = sigt, mpp = sigp, mtn = sigt, mnn = sign_;

  int ntiles = (ns + 15) >> 4;   // 16 rows per "tile" (1 row per warp)

  for (int it = 0; it < ITMAX; ++it) {
    // publish search directions
    s_pp[tid] = pp; s_pn[tid] = pn;
    __syncthreads();

    // p slices in registers (float4); thread's columns are 4*(lane+32k)+0..3
    float4 ppv[4], pnv[4];
    #pragma unroll
    for (int k = 0; k < 4; k++) {
      ppv[k] = ((const float4*)s_pp)[lane + 32 * k];
      pnv[k] = ((const float4*)s_pn)[lane + 32 * k];
    }

    // per-thread partial Ap accumulators over this thread's 16 columns
    float4 accp[4], accn[4];
    #pragma unroll
    for (int k = 0; k < 4; k++) {
      accp[k] = make_float4(0.f, 0.f, 0.f, 0.f);
      accn[k] = make_float4(0.f, 0.f, 0.f, 0.f);
    }

    // barrier-free row loop: warp w handles rows w, w+16, w+32, ...
    for (int t = 0; t < ntiles; t++) {
      int j = t * 16 + w;
      if (j < ns) {                       // warp-uniform branch
        float4 xv[4];
        if (j < CROWS) {                  // warp-uniform (compile-time vs j)
          const float4* row4 = (const float4*)(s_cache + (size_t)j * ND);
          #pragma unroll
          for (int k = 0; k < 4; k++) xv[k] = row4[lane + 32 * k];
        } else {
          const float4* row4 = (const float4*)(X + (size_t)s_idx[j] * ND);
          #pragma unroll
          for (int k = 0; k < 4; k++) xv[k] = __ldg(&row4[lane + 32 * k]);
        }
        float ap = 0.f, an = 0.f;
        #pragma unroll
        for (int k = 0; k < 4; k++) {
          ap += xv[k].x * ppv[k].x + xv[k].y * ppv[k].y + xv[k].z * ppv[k].z + xv[k].w * ppv[k].w;
          an += xv[k].x * pnv[k].x + xv[k].y * pnv[k].y + xv[k].z * pnv[k].z + xv[k].w * pnv[k].w;
        }
        #pragma unroll
        for (int o = 16; o; o >>= 1) {
          ap += __shfl_down_sync(0xffffffffu, ap, o);
          an += __shfl_down_sync(0xffffffffu, an, o);
        }
        ap = __shfl_sync(0xffffffffu, ap, 0);
        an = __shfl_sync(0xffffffffu, an, 0);
        float ep = s_cp[j] * ap;          // broadcast smem read
        float en = s_cn[j] * an;
        #pragma unroll
        for (int k = 0; k < 4; k++) {
          accp[k].x += ep * xv[k].x; accp[k].y += ep * xv[k].y;
          accp[k].z += ep * xv[k].z; accp[k].w += ep * xv[k].w;
          accn[k].x += en * xv[k].x; accn[k].y += en * xv[k].y;
          accn[k].z += en * xv[k].z; accn[k].w += en * xv[k].w;
        }
      }
    }

    // cross-warp partial reduction, two rounds through [16][ND].
    // Round P: safe without leading barrier (prior reads fenced by loop-head
    // barrier of this iteration).
    #pragma unroll
    for (int k = 0; k < 4; k++)
      ((float4*)(s_part + (size_t)w * ND))[lane + 32 * k] = accp[k];
    __syncthreads();
    float apr = 0.f;
    #pragma unroll
    for (int w2 = 0; w2 < 16; w2++) apr += s_part[(size_t)w2 * ND + tid];
    __syncthreads();                    // reads done before round N overwrites
    #pragma unroll
    for (int k = 0; k < 4; k++)
      ((float4*)(s_part + (size_t)w * ND))[lane + 32 * k] = accn[k];
    __syncthreads();
    float anr = 0.f;
    #pragma unroll
    for (int w2 = 0; w2 < 16; w2++) anr += s_part[(size_t)w2 * ND + tid];

    // q = M p (rank-1 mean corrections; mu.p exact via one-step identity)
    float qp = apr + 0.1f * pp - wmt * mtp * mt - wmp * mpp * mp_;
    float qn = anr + 0.1f * pn - wmt * mtn * mt - wmn * mnn * mn_;

    // direct p.q reduction -> alpha  (redK's first barrier also fences the
    // round-N s_part reads above)
    v2[0] = pp * qp; v2[1] = pn * qn;
    redK<2>(s_red, v2, o2, lane, w, tid);
    float alp = rsp / o2[0], aln = rsn / o2[1];
    xp += alp * pp;  rp -= alp * qp;
    xn += aln * pn;  rn -= aln * qn;

    // direct ||r_new||^2 + FRESH mu.r_new, all in one reduction
    v6[0] = rp * rp; v6[1] = rn * rn;
    v6[2] = mt * rp; v6[3] = mp_ * rp;
    v6[4] = mt * rn; v6[5] = mn_ * rn;
    redK<6>(s_red, v6, o6, lane, w, tid);
    float bp = o6[0] / rsp, bn = o6[1] / rsn;
    rsp = o6[0]; rsn = o6[1];
    pp = rp + bp * pp;  pn = rn + bn * pn;
    // mu.p_new = mu.r_new (fresh) + beta * mu.p_old  (exact identity)
    mtp = o6[2] + bp * mtp;  mpp = o6[3] + bp * mpp;
    mtn = o6[4] + bn * mtn;  mnn = o6[5] + bn * mnn;
    if (rsp < CG_TOL && rsn < CG_TOL) break;   // uniform across CTA
  }

  g_rr[b][0][tid] = xp;
  g_rr[b][1][tid] = xn;
  v2[0] = mp_ * xp; v2[1] = mn_ * xn;
  redK<2>(s_red, v2, o2, lane, w, tid);
  if (tid == 0) {
    g_sc[b][0] = o2[0]; g_sc[b][1] = sigp;
    g_sc[b][2] = o2[1]; g_sc[b][3] = sign_;
  }
}

// ---------------------------------------------------------------------------
// Kernel 4: outputs. maha = (q.r - mu.r) * (sum(q) - sum(mu)).
// grid (NB, 8) x 512 threads, float4 loads (more CTAs -> latency hiding).
// ---------------------------------------------------------------------------
__global__ void out_kernel(const float* __restrict__ X, const float* __restrict__ log_scale,
                           float* __restrict__ out) {
  __shared__ float s_rp[ND];
  __shared__ float s_rn[ND];
  __shared__ float s_s[8];
  int b = blockIdx.x, part = blockIdx.y, tid = threadIdx.x;
  s_rp[tid] = g_rr[b][0][tid];
  s_rn[tid] = g_rr[b][1][tid];
  if (tid < 4) s_s[tid] = g_sc[b][tid];
  if (tid == 4) s_s[4] = expf(log_scale[0]);
  __syncthreads();
  int nq = g_cnt[b][2];
  int w = tid >> 5, lane = tid & 31;
  const float4* rp4 = (const float4*)s_rp;
  const float4* rn4 = (const float4*)s_rn;
  #pragma unroll
  for (int rep = 0; rep < 4; rep++) {
    int i = part * 64 + rep * 16 + w;
    if (i < nq) {
      int gj = g_qry_idx[b][i];
      const float4* q4 = (const float4*)(X + (size_t)gj * ND);
      float aqr = 0.f, aqn = 0.f, aqs = 0.f;
      #pragma unroll
      for (int k = 0; k < 4; k++) {
        float4 v = q4[lane + 32 * k];
        float4 a = rp4[lane + 32 * k];
        float4 c = rn4[lane + 32 * k];
        aqr += v.x * a.x + v.y * a.y + v.z * a.z + v.w * a.w;
        aqn += v.x * c.x + v.y * c.y + v.z * c.z + v.w * c.w;
        aqs += v.x + v.y + v.z + v.w;
      }
      #pragma unroll
      for (int o = 16; o; o >>= 1) {
        aqr += __shfl_down_sync(0xffffffffu, aqr, o);
        aqn += __shfl_down_sync(0xffffffffu, aqn, o);
        aqs += __shfl_down_sync(0xffffffffu, aqs, o);
      }
      if (lane == 0) {
        float sc = s_s[4];
        float sp = aqr - s_s[0], tp = aqs - s_s[1];
        float sn = aqn - s_s[2], tn = aqs - s_s[3];
        size_t o0 = ((size_t)b * NL + i) * 2;
        out[o0]     = sn * tn * sc;   // neg logit
        out[o0 + 1] = sp * tp * sc;   // pos logit
      }
    } else if (lane == 0) {
      size_t o0 = ((size_t)b * NL + i) * 2;
      out[o0] = 0.f; out[o0 + 1] = 0.f;
    }
  }
}

// ---------------------------------------------------------------------------
// Inputs (metadata order): graph_reprs f32[N*512], log_scale f32[1],
// labels i32[N], is_query i32[N], batch_index i32[N] (sorted).
// Output: f32[128*512*2].
// ---------------------------------------------------------------------------
extern "C" void kernel_launch(void* const* d_in, const int* in_sizes, int n_in,
                              void* d_out, int out_size) {
  const float* X      = (const float*)d_in[0];
  const float* logsc  = (const float*)d_in[1];
  const int*   labels = (const int*)d_in[2];
  const int*   isq    = (const int*)d_in[3];
  const int*   bidx   = (const int*)d_in[4];
  int N = in_sizes[2];

  cudaFuncSetAttribute(cg_kernel, cudaFuncAttributeMaxDynamicSharedMemorySize, CG_SMEM_BYTES);

  seg_kernel<<<NB, 32>>>(bidx, isq, labels, N);
  mean_kernel<<<dim3(NB, NPART), ND>>>(X);
  cg_kernel<<<NB, ND, CG_SMEM_BYTES>>>(X);
  out_kernel<<<dim3(NB, 8), 512>>>(X, logsc, (float*)d_out);
}

// round 15
// speedup vs baseline: 2.5156x; 1.0597x over previous
#include <cuda_runtime.h>
#include <cstdint>
#include <math.h>

// Problem constants: B=128 episodes, L=512 pad, D=512 dims.
#define NB 128
#define NL 512
#define ND 512
#define NPART 8
#define ITMAX 64
#define CROWS 88        // support rows cached persistently in smem
#define CG_TOL 1e-2f    // on squared residual norm: ||r|| <= ~0.1 (rel_err ~ 2e-4)

typedef unsigned long long u64;

// Packed f32x2 helpers (sm_103a FFMA2 — only reachable via explicit PTX)
__device__ __forceinline__ u64 fma2(u64 a, u64 b, u64 c) {
  u64 d;
  asm("fma.rn.f32x2 %0, %1, %2, %3;" : "=l"(d) : "l"(a), "l"(b), "l"(c));
  return d;
}
__device__ __forceinline__ float2 unpack2(u64 v) {
  float2 f; asm("mov.b64 {%0, %1}, %2;" : "=f"(f.x), "=f"(f.y) : "l"(v)); return f;
}
__device__ __forceinline__ u64 pack2(float x, float y) {
  u64 v; asm("mov.b64 %0, {%1, %2};" : "=l"(v) : "f"(x), "f"(y)); return v;
}

// Scratch (__device__ globals; no allocations allowed)
__device__ int   g_sup_idx[NB][NL];
__device__ int   g_sup_lab[NB][NL];
__device__ int   g_qry_idx[NB][NL];
__device__ int   g_cnt[NB][4];              // [0]=ns, [1]=np, [2]=nq
__device__ float g_musum[NB][NPART][2][ND]; // per-part partial sums: task, pos
__device__ float g_rr[NB][2][ND];           // x_pos, x_neg  (= M^{-1} @ 1)
__device__ float g_sc[NB][4];               // mu_p.x_p, sum(mu_p), mu_n.x_n, sum(mu_n)

// ---------------------------------------------------------------------------
// Kernel 1: segmentation. batch_index is sorted -> contiguous episode ranges;
// stable split into support/query. One warp per episode.
// ---------------------------------------------------------------------------
__global__ void seg_kernel(const int* __restrict__ bidx, const int* __restrict__ isq,
                           const int* __restrict__ labels, int N) {
  int b = blockIdx.x;
  int lane = threadIdx.x;
  int start = 0, end = 0;
  if (lane == 0) {
    int lo = 0, hi = N;
    while (lo < hi) { int m = (lo + hi) >> 1; if (bidx[m] < b) lo = m + 1; else hi = m; }
    start = lo; hi = N;
    while (lo < hi) { int m = (lo + hi) >> 1; if (bidx[m] <= b) lo = m + 1; else hi = m; }
    end = lo;
  }
  start = __shfl_sync(0xffffffffu, start, 0);
  end   = __shfl_sync(0xffffffffu, end, 0);

  int sbase = 0, qbase = 0, pcnt = 0;
  for (int k0 = start; k0 < end; k0 += 32) {
    int k = k0 + lane;
    bool valid = k < end;
    int q  = valid ? isq[k]    : 0;
    int lb = valid ? labels[k] : 0;
    unsigned mq = __ballot_sync(0xffffffffu, valid && q != 0);
    unsigned ms = __ballot_sync(0xffffffffu, valid && q == 0);
    unsigned mp = __ballot_sync(0xffffffffu, valid && q == 0 && lb != 0);
    unsigned lt = (1u << lane) - 1u;
    if (valid) {
      if (q != 0) {
        int r = qbase + __popc(mq & lt);
        if (r < NL) g_qry_idx[b][r] = k;
      } else {
        int r = sbase + __popc(ms & lt);
        if (r < NL) { g_sup_idx[b][r] = k; g_sup_lab[b][r] = lb; }
      }
    }
    qbase += __popc(mq); sbase += __popc(ms); pcnt += __popc(mp);
  }
  if (lane == 0) {
    g_cnt[b][0] = min(sbase, NL);
    g_cnt[b][1] = pcnt;
    g_cnt[b][2] = min(qbase, NL);
  }
}

// ---------------------------------------------------------------------------
// Kernel 2: per-episode partial mean sums. grid (NB, NPART).
// ---------------------------------------------------------------------------
__global__ void mean_kernel(const float* __restrict__ X) {
  int b = blockIdx.x, part = blockIdx.y, d = threadIdx.x;
  int ns = g_cnt[b][0];
  float s = 0.f, sp = 0.f;
  for (int j = part; j < ns; j += NPART) {
    int idx = g_sup_idx[b][j];
    int lb  = g_sup_lab[b][j];
    float v = __ldg(&X[(size_t)idx * ND + d]);
    s += v;
    if (lb) sp += v;
  }
  g_musum[b][part][0][d] = s;
  g_musum[b][part][1][d] = sp;
}

// ---------------------------------------------------------------------------
// K-wide block reduction over 512 threads, trailing barrier included.
// ---------------------------------------------------------------------------
template <int K>
__device__ __forceinline__ void redK(float* s_red, float v[K], float out[K],
                                     int lane, int w, int tid) {
  #pragma unroll
  for (int o = 16; o; o >>= 1) {
    #pragma unroll
    for (int i = 0; i < K; i++) v[i] += __shfl_down_sync(0xffffffffu, v[i], o);
  }
  if (lane == 0) {
    #pragma unroll
    for (int i = 0; i < K; i++) s_red[w * K + i] = v[i];
  }
  __syncthreads();
  if (tid < K) {
    float s = 0.f;
    #pragma unroll
    for (int w2 = 0; w2 < 16; w2++) s += s_red[w2 * K + tid];
    s_red[16 * K + tid] = s;
  }
  __syncthreads();
  #pragma unroll
  for (int i = 0; i < K; i++) out[i] = s_red[16 * K + i];
  __syncthreads();
}

// ---------------------------------------------------------------------------
// Kernel 3: fused CG, register-resident matvec (packed f32x2) + persistent
// smem row cache. CG scalar math IDENTICAL to R11-R14 (direct rs, direct
// p.q, fresh mu.r). Dot + rank-1 accumulate use fma.rn.f32x2 (FFMA2):
// halves the FMA issue count of the hot loop. Warp reduction via shfl_xor
// butterfly (all lanes get the sum; no broadcast needed).
// ---------------------------------------------------------------------------
#define CG_SMEM_FLOATS (2*ND + 2*NL + NL + 16*ND + 128 + CROWS*ND)
#define CG_SMEM_BYTES  (CG_SMEM_FLOATS * 4)

__global__ __launch_bounds__(512, 1) void cg_kernel(const float* __restrict__ X) {
  extern __shared__ float smem[];
  float* s_pp  = smem;                  // [ND]
  float* s_pn  = s_pp + ND;             // [ND]
  float* s_cp  = s_pn + ND;             // [NL]
  float* s_cn  = s_cp + NL;             // [NL]
  int*   s_idx = (int*)(s_cn + NL);     // [NL]
  float* s_part= (float*)(s_idx + NL);  // [16][ND]
  float* s_red = s_part + 16 * ND;      // [128]
  float* s_cache = s_red + 128;         // [CROWS][ND]

  int b = blockIdx.x, tid = threadIdx.x, lane = tid & 31, w = tid >> 5;
  int ns = g_cnt[b][0], np = g_cnt[b][1];
  float fns = (float)ns, fnp = (float)np, fnn = (float)(ns - np);
  float wt  = 0.9f / (fns - 1.f), wmt = 0.9f * fns / (fns - 1.f);
  float wp  = 0.1f / (fnp - 1.f), wmp = 0.1f * fnp / (fnp - 1.f);
  float wn  = 0.1f / (fnn - 1.f), wmn = 0.1f * fnn / (fnn - 1.f);

  for (int j = tid; j < ns; j += 512) {
    s_idx[j] = g_sup_idx[b][j];
    int lb = g_sup_lab[b][j];
    s_cp[j] = wt + (lb ? wp : 0.f);
    s_cn[j] = wt + (lb ? 0.f : wn);
  }
  // fill persistent row cache with cp.async (rows 0..min(ns,CROWS)-1)
  {
    int cr = min(ns, CROWS);
    for (int i4 = tid; i4 < cr * 128; i4 += 512) {
      int r = i4 >> 7, c = i4 & 127;
      int gj = g_sup_idx[b][r];
      const float* src = X + (size_t)gj * ND + c * 4;
      unsigned dst = (unsigned)__cvta_generic_to_shared(&s_cache[(size_t)r * ND + c * 4]);
      asm volatile("cp.async.cg.shared.global [%0], [%1], 16;" :: "r"(dst), "l"(src));
    }
    asm volatile("cp.async.commit_group;");
    asm volatile("cp.async.wait_group 0;");
  }
  // means from partial sums
  float s0 = 0.f, s1 = 0.f;
  #pragma unroll
  for (int p = 0; p < NPART; p++) { s0 += g_musum[b][p][0][tid]; s1 += g_musum[b][p][1][tid]; }
  float mt  = s0 / fns;
  float mp_ = s1 / fnp;
  float mn_ = (s0 - s1) / fnn;

  // CG state (thread d owns component d); solve M x = 1 for pos & neg systems
  float xp = 0.f, xn = 0.f, rp = 1.f, rn = 1.f, pp = 1.f, pn = 1.f;
  float rsp = (float)ND, rsn = (float)ND;

  float v6[6], o6[6], v2[2], o2[2];
  #pragma unroll
  for (int i = 0; i < 6; i++) v6[i] = 0.f;
  v6[0] = mt; v6[1] = mp_; v6[2] = mn_;
  redK<6>(s_red, v6, o6, lane, w, tid);   // barriers fence s_idx/s_cp/s_cn/cache
  float sigt = o6[0], sigp = o6[1], sign_ = o6[2];
  // mu.p for each system (p0 = ones)
  float mtp = sigt, mpp = sigp, mtn = sigt, mnn = sign_;

  int ntiles = (ns + 15) >> 4;   // 16 rows per "tile" (1 row per warp)

  for (int it = 0; it < ITMAX; ++it) {
    // publish search directions
    s_pp[tid] = pp; s_pn[tid] = pn;
    __syncthreads();

    // p slices in packed u64 pairs; thread's 16 columns = float4 idx lane+32k
    u64 pp2[8], pn2[8];
    #pragma unroll
    for (int k = 0; k < 4; k++) {
      ulonglong2 a = ((const ulonglong2*)s_pp)[lane + 32 * k];
      ulonglong2 c = ((const ulonglong2*)s_pn)[lane + 32 * k];
      pp2[2 * k] = a.x; pp2[2 * k + 1] = a.y;
      pn2[2 * k] = c.x; pn2[2 * k + 1] = c.y;
    }

    // per-thread packed partial-Ap accumulators (16 columns = 8 u64 lanes)
    u64 accp2[8], accn2[8];
    #pragma unroll
    for (int k = 0; k < 8; k++) { accp2[k] = 0ull; accn2[k] = 0ull; }  // bits0 = (0.f,0.f)

    // barrier-free row loop: warp w handles rows w, w+16, w+32, ...
    for (int t = 0; t < ntiles; t++) {
      int j = t * 16 + w;
      if (j < ns) {                       // warp-uniform branch
        u64 xv2[8];
        if (j < CROWS) {                  // warp-uniform
          const ulonglong2* row2 = (const ulonglong2*)(s_cache + (size_t)j * ND);
          #pragma unroll
          for (int k = 0; k < 4; k++) {
            ulonglong2 v = row2[lane + 32 * k];
            xv2[2 * k] = v.x; xv2[2 * k + 1] = v.y;
          }
        } else {
          const ulonglong2* row2 = (const ulonglong2*)(X + (size_t)s_idx[j] * ND);
          #pragma unroll
          for (int k = 0; k < 4; k++) {
            ulonglong2 v = __ldg(&row2[lane + 32 * k]);
            xv2[2 * k] = v.x; xv2[2 * k + 1] = v.y;
          }
        }
        // packed dot products (8 FFMA2 per system)
        u64 dp2 = 0ull, dn2 = 0ull;
        #pragma unroll
        for (int k = 0; k < 8; k++) {
          dp2 = fma2(xv2[k], pp2[k], dp2);
          dn2 = fma2(xv2[k], pn2[k], dn2);
        }
        float2 fp = unpack2(dp2), fn = unpack2(dn2);
        float ap = fp.x + fp.y, an = fn.x + fn.y;
        // butterfly: all lanes end with the row sum
        #pragma unroll
        for (int o = 16; o; o >>= 1) {
          ap += __shfl_xor_sync(0xffffffffu, ap, o);
          an += __shfl_xor_sync(0xffffffffu, an, o);
        }
        float ep = s_cp[j] * ap;          // broadcast smem read
        float en = s_cn[j] * an;
        u64 e2p = pack2(ep, ep), e2n = pack2(en, en);
        // packed rank-1 accumulate (8 FFMA2 per system)
        #pragma unroll
        for (int k = 0; k < 8; k++) {
          accp2[k] = fma2(e2p, xv2[k], accp2[k]);
          accn2[k] = fma2(e2n, xv2[k], accn2[k]);
        }
      }
    }

    // cross-warp partial reduction, two rounds through [16][ND].
    // Round P: safe without leading barrier (prior reads fenced by loop-head
    // barrier of this iteration).
    #pragma unroll
    for (int k = 0; k < 4; k++)
      ((ulonglong2*)(s_part + (size_t)w * ND))[lane + 32 * k] =
          make_ulonglong2(accp2[2 * k], accp2[2 * k + 1]);
    __syncthreads();
    float apr = 0.f;
    #pragma unroll
    for (int w2 = 0; w2 < 16; w2++) apr += s_part[(size_t)w2 * ND + tid];
    __syncthreads();                    // reads done before round N overwrites
    #pragma unroll
    for (int k = 0; k < 4; k++)
      ((ulonglong2*)(s_part + (size_t)w * ND))[lane + 32 * k] =
          make_ulonglong2(accn2[2 * k], accn2[2 * k + 1]);
    __syncthreads();
    float anr = 0.f;
    #pragma unroll
    for (int w2 = 0; w2 < 16; w2++) anr += s_part[(size_t)w2 * ND + tid];

    // q = M p (rank-1 mean corrections; mu.p exact via one-step identity)
    float qp = apr + 0.1f * pp - wmt * mtp * mt - wmp * mpp * mp_;
    float qn = anr + 0.1f * pn - wmt * mtn * mt - wmn * mnn * mn_;

    // direct p.q reduction -> alpha  (redK's first barrier also fences the
    // round-N s_part reads above)
    v2[0] = pp * qp; v2[1] = pn * qn;
    redK<2>(s_red, v2, o2, lane, w, tid);
    float alp = rsp / o2[0], aln = rsn / o2[1];
    xp += alp * pp;  rp -= alp * qp;
    xn += aln * pn;  rn -= aln * qn;

    // direct ||r_new||^2 + FRESH mu.r_new, all in one reduction
    v6[0] = rp * rp; v6[1] = rn * rn;
    v6[2] = mt * rp; v6[3] = mp_ * rp;
    v6[4] = mt * rn; v6[5] = mn_ * rn;
    redK<6>(s_red, v6, o6, lane, w, tid);
    float bp = o6[0] / rsp, bn = o6[1] / rsn;
    rsp = o6[0]; rsn = o6[1];
    pp = rp + bp * pp;  pn = rn + bn * pn;
    // mu.p_new = mu.r_new (fresh) + beta * mu.p_old  (exact identity)
    mtp = o6[2] + bp * mtp;  mpp = o6[3] + bp * mpp;
    mtn = o6[4] + bn * mtn;  mnn = o6[5] + bn * mnn;
    if (rsp < CG_TOL && rsn < CG_TOL) break;   // uniform across CTA
  }

  g_rr[b][0][tid] = xp;
  g_rr[b][1][tid] = xn;
  v2[0] = mp_ * xp; v2[1] = mn_ * xn;
  redK<2>(s_red, v2, o2, lane, w, tid);
  if (tid == 0) {
    g_sc[b][0] = o2[0]; g_sc[b][1] = sigp;
    g_sc[b][2] = o2[1]; g_sc[b][3] = sign_;
  }
}

// ---------------------------------------------------------------------------
// Kernel 4: outputs. maha = (q.r - mu.r) * (sum(q) - sum(mu)).
// grid (NB, 8) x 512 threads, float4 loads.
// ---------------------------------------------------------------------------
__global__ void out_kernel(const float* __restrict__ X, const float* __restrict__ log_scale,
                           float* __restrict__ out) {
  __shared__ float s_rp[ND];
  __shared__ float s_rn[ND];
  __shared__ float s_s[8];
  int b = blockIdx.x, part = blockIdx.y, tid = threadIdx.x;
  s_rp[tid] = g_rr[b][0][tid];
  s_rn[tid] = g_rr[b][1][tid];
  if (tid < 4) s_s[tid] = g_sc[b][tid];
  if (tid == 4) s_s[4] = expf(log_scale[0]);
  __syncthreads();
  int nq = g_cnt[b][2];
  int w = tid >> 5, lane = tid & 31;
  const float4* rp4 = (const float4*)s_rp;
  const float4* rn4 = (const float4*)s_rn;
  #pragma unroll
  for (int rep = 0; rep < 4; rep++) {
    int i = part * 64 + rep * 16 + w;
    if (i < nq) {
      int gj = g_qry_idx[b][i];
      const float4* q4 = (const float4*)(X + (size_t)gj * ND);
      float aqr = 0.f, aqn = 0.f, aqs = 0.f;
      #pragma unroll
      for (int k = 0; k < 4; k++) {
        float4 v = q4[lane + 32 * k];
        float4 a = rp4[lane + 32 * k];
        float4 c = rn4[lane + 32 * k];
        aqr += v.x * a.x + v.y * a.y + v.z * a.z + v.w * a.w;
        aqn += v.x * c.x + v.y * c.y + v.z * c.z + v.w * c.w;
        aqs += v.x + v.y + v.z + v.w;
      }
      #pragma unroll
      for (int o = 16; o; o >>= 1) {
        aqr += __shfl_down_sync(0xffffffffu, aqr, o);
        aqn += __shfl_down_sync(0xffffffffu, aqn, o);
        aqs += __shfl_down_sync(0xffffffffu, aqs, o);
      }
      if (lane == 0) {
        float sc = s_s[4];
        float sp = aqr - s_s[0], tp = aqs - s_s[1];
        float sn = aqn - s_s[2], tn = aqs - s_s[3];
        size_t o0 = ((size_t)b * NL + i) * 2;
        out[o0]     = sn * tn * sc;   // neg logit
        out[o0 + 1] = sp * tp * sc;   // pos logit
      }
    } else if (lane == 0) {
      size_t o0 = ((size_t)b * NL + i) * 2;
      out[o0] = 0.f; out[o0 + 1] = 0.f;
    }
  }
}

// ---------------------------------------------------------------------------
// Inputs (metadata order): graph_reprs f32[N*512], log_scale f32[1],
// labels i32[N], is_query i32[N], batch_index i32[N] (sorted).
// Output: f32[128*512*2].
// ---------------------------------------------------------------------------
extern "C" void kernel_launch(void* const* d_in, const int* in_sizes, int n_in,
                              void* d_out, int out_size) {
  const float* X      = (const float*)d_in[0];
  const float* logsc  = (const float*)d_in[1];
  const int*   labels = (const int*)d_in[2];
  const int*   isq    = (const int*)d_in[3];
  const int*   bidx   = (const int*)d_in[4];
  int N = in_sizes[2];

  cudaFuncSetAttribute(cg_kernel, cudaFuncAttributeMaxDynamicSharedMemorySize, CG_SMEM_BYTES);

  seg_kernel<<<NB, 32>>>(bidx, isq, labels, N);
  mean_kernel<<<dim3(NB, NPART), ND>>>(X);
  cg_kernel<<<NB, ND, CG_SMEM_BYTES>>>(X);
  out_kernel<<<dim3(NB, 8), 512>>>(X, logsc, (float*)d_out);
}

// round 17
// speedup vs baseline: 2.5608x; 1.0180x over previous
#include <cuda_runtime.h>
#include <cstdint>
#include <math.h>

// Problem constants: B=128 episodes, L=512 pad, D=512 dims.
#define NB 128
#define NL 512
#define ND 512
#define NPART 8
#define ITMAX 64
#define CROWS 88        // support rows cached persistently in smem
#define RROWS 16        // rows CROWS..CROWS+15 cached in registers (1/warp)
#define CG_TOL 2e-2f    // on squared residual norm: ||r|| <= ~0.14 (rel_err ~ 3e-4)

typedef unsigned long long u64;

// Packed f32x2 helpers (sm_103a FFMA2 — only reachable via explicit PTX)
__device__ __forceinline__ u64 fma2(u64 a, u64 b, u64 c) {
  u64 d;
  asm("fma.rn.f32x2 %0, %1, %2, %3;" : "=l"(d) : "l"(a), "l"(b), "l"(c));
  return d;
}
__device__ __forceinline__ float2 unpack2(u64 v) {
  float2 f; asm("mov.b64 {%0, %1}, %2;" : "=f"(f.x), "=f"(f.y) : "l"(v)); return f;
}
__device__ __forceinline__ u64 pack2(float x, float y) {
  u64 v; asm("mov.b64 %0, {%1, %2};" : "=l"(v) : "f"(x), "f"(y)); return v;
}

// Scratch (__device__ globals; no allocations allowed)
__device__ int   g_sup_idx[NB][NL];
__device__ int   g_sup_lab[NB][NL];
__device__ int   g_qry_idx[NB][NL];
__device__ int   g_cnt[NB][4];              // [0]=ns, [1]=np, [2]=nq
__device__ float g_musum[NB][NPART][2][ND]; // per-part partial sums: task, pos
__device__ float g_rr[NB][2][ND];           // x_pos, x_neg  (= M^{-1} @ 1)
__device__ float g_sc[NB][4];               // mu_p.x_p, sum(mu_p), mu_n.x_n, sum(mu_n)

// ---------------------------------------------------------------------------
// Kernel 1: segmentation. batch_index is sorted -> contiguous episode ranges;
// stable split into support/query. One warp per episode.
// ---------------------------------------------------------------------------
__global__ void seg_kernel(const int* __restrict__ bidx, const int* __restrict__ isq,
                           const int* __restrict__ labels, int N) {
  int b = blockIdx.x;
  int lane = threadIdx.x;
  int start = 0, end = 0;
  if (lane == 0) {
    int lo = 0, hi = N;
    while (lo < hi) { int m = (lo + hi) >> 1; if (bidx[m] < b) lo = m + 1; else hi = m; }
    start = lo; hi = N;
    while (lo < hi) { int m = (lo + hi) >> 1; if (bidx[m] <= b) lo = m + 1; else hi = m; }
    end = lo;
  }
  start = __shfl_sync(0xffffffffu, start, 0);
  end   = __shfl_sync(0xffffffffu, end, 0);

  int sbase = 0, qbase = 0, pcnt = 0;
  for (int k0 = start; k0 < end; k0 += 32) {
    int k = k0 + lane;
    bool valid = k < end;
    int q  = valid ? isq[k]    : 0;
    int lb = valid ? labels[k] : 0;
    unsigned mq = __ballot_sync(0xffffffffu, valid && q != 0);
    unsigned ms = __ballot_sync(0xffffffffu, valid && q == 0);
    unsigned mp = __ballot_sync(0xffffffffu, valid && q == 0 && lb != 0);
    unsigned lt = (1u << lane) - 1u;
    if (valid) {
      if (q != 0) {
        int r = qbase + __popc(mq & lt);
        if (r < NL) g_qry_idx[b][r] = k;
      } else {
        int r = sbase + __popc(ms & lt);
        if (r < NL) { g_sup_idx[b][r] = k; g_sup_lab[b][r] = lb; }
      }
    }
    qbase += __popc(mq); sbase += __popc(ms); pcnt += __popc(mp);
  }
  if (lane == 0) {
    g_cnt[b][0] = min(sbase, NL);
    g_cnt[b][1] = pcnt;
    g_cnt[b][2] = min(qbase, NL);
  }
}

// ---------------------------------------------------------------------------
// Kernel 2: per-episode partial mean sums. grid (NB, NPART).
// ---------------------------------------------------------------------------
__global__ void mean_kernel(const float* __restrict__ X) {
  int b = blockIdx.x, part = blockIdx.y, d = threadIdx.x;
  int ns = g_cnt[b][0];
  float s = 0.f, sp = 0.f;
  for (int j = part; j < ns; j += NPART) {
    int idx = g_sup_idx[b][j];
    int lb  = g_sup_lab[b][j];
    float v = __ldg(&X[(size_t)idx * ND + d]);
    s += v;
    if (lb) sp += v;
  }
  g_musum[b][part][0][d] = s;
  g_musum[b][part][1][d] = sp;
}

// ---------------------------------------------------------------------------
// K-wide block reduction over 512 threads, trailing barrier included.
// ---------------------------------------------------------------------------
template <int K>
__device__ __forceinline__ void redK(float* s_red, float v[K], float out[K],
                                     int lane, int w, int tid) {
  #pragma unroll
  for (int o = 16; o; o >>= 1) {
    #pragma unroll
    for (int i = 0; i < K; i++) v[i] += __shfl_down_sync(0xffffffffu, v[i], o);
  }
  if (lane == 0) {
    #pragma unroll
    for (int i = 0; i < K; i++) s_red[w * K + i] = v[i];
  }
  __syncthreads();
  if (tid < K) {
    float s = 0.f;
    #pragma unroll
    for (int w2 = 0; w2 < 16; w2++) s += s_red[w2 * K + tid];
    s_red[16 * K + tid] = s;
  }
  __syncthreads();
  #pragma unroll
  for (int i = 0; i < K; i++) out[i] = s_red[16 * K + i];
  __syncthreads();
}

// ---------------------------------------------------------------------------
// Kernel 3: fused CG, register-resident matvec (packed f32x2) + smem row
// cache (rows < CROWS) + register row cache (rows CROWS..CROWS+15, one per
// warp via j = w mod 16). CG scalar math: direct rs; alpha now from IN-LOOP
// p.q: p.A_data.p = sum_j c_j d_j^2 accumulated per warp while d_j is live,
// combined with 0.1*||p||^2 (||p_new||^2 = rs_new + beta^2*||p_old||^2,
// ||p_old||^2 freshly MEASURED in the tail redK8 each iteration) and the
// mean-correction scalars. Removes the mid-iteration redK2 entirely.
// ---------------------------------------------------------------------------
#define CG_SMEM_FLOATS (2*ND + 2*NL + NL + 16*ND + 160 + 32 + CROWS*ND)
#define CG_SMEM_BYTES  (CG_SMEM_FLOATS * 4)

__global__ __launch_bounds__(512, 1) void cg_kernel(const float* __restrict__ X) {
  extern __shared__ float smem[];
  float* s_pp  = smem;                  // [ND]
  float* s_pn  = s_pp + ND;             // [ND]
  float* s_cp  = s_pn + ND;             // [NL]
  float* s_cn  = s_cp + NL;             // [NL]
  int*   s_idx = (int*)(s_cn + NL);     // [NL]
  float* s_part= (float*)(s_idx + NL);  // [16][ND]
  float* s_red = s_part + 16 * ND;      // [160]
  float* s_scal= s_red + 160;           // [32]: warp partials of c_j d_j^2
  float* s_cache = s_scal + 32;         // [CROWS][ND]

  int b = blockIdx.x, tid = threadIdx.x, lane = tid & 31, w = tid >> 5;
  int ns = g_cnt[b][0], np = g_cnt[b][1];
  float fns = (float)ns, fnp = (float)np, fnn = (float)(ns - np);
  float wt  = 0.9f / (fns - 1.f), wmt = 0.9f * fns / (fns - 1.f);
  float wp  = 0.1f / (fnp - 1.f), wmp = 0.1f * fnp / (fnp - 1.f);
  float wn  = 0.1f / (fnn - 1.f), wmn = 0.1f * fnn / (fnn - 1.f);

  for (int j = tid; j < ns; j += 512) {
    s_idx[j] = g_sup_idx[b][j];
    int lb = g_sup_lab[b][j];
    s_cp[j] = wt + (lb ? wp : 0.f);
    s_cn[j] = wt + (lb ? 0.f : wn);
  }
  // fill persistent smem row cache with cp.async (rows 0..min(ns,CROWS)-1)
  {
    int cr = min(ns, CROWS);
    for (int i4 = tid; i4 < cr * 128; i4 += 512) {
      int r = i4 >> 7, c = i4 & 127;
      int gj = g_sup_idx[b][r];
      const float* src = X + (size_t)gj * ND + c * 4;
      unsigned dst = (unsigned)__cvta_generic_to_shared(&s_cache[(size_t)r * ND + c * 4]);
      asm volatile("cp.async.cg.shared.global [%0], [%1], 16;" :: "r"(dst), "l"(src));
    }
    asm volatile("cp.async.commit_group;");
    asm volatile("cp.async.wait_group 0;");
  }
  // register row cache: warp w owns the unique row in [CROWS, CROWS+16)
  // with j == w (mod 16).
  int jreg = CROWS + ((w - (CROWS & 15) + 16) & 15);   // j in [CROWS, CROWS+16), j%16==w
  u64 xr2[8];
  bool has_reg = jreg < ns;
  if (has_reg) {
    int gjr;
    if (tid < NL) {}  // no-op
    gjr = g_sup_idx[b][jreg];
    const ulonglong2* row2 = (const ulonglong2*)(X + (size_t)gjr * ND);
    #pragma unroll
    for (int k = 0; k < 4; k++) {
      ulonglong2 v = __ldg(&row2[lane + 32 * k]);
      xr2[2 * k] = v.x; xr2[2 * k + 1] = v.y;
    }
  }
  // means from partial sums
  float s0 = 0.f, s1 = 0.f;
  #pragma unroll
  for (int p = 0; p < NPART; p++) { s0 += g_musum[b][p][0][tid]; s1 += g_musum[b][p][1][tid]; }
  float mt  = s0 / fns;
  float mp_ = s1 / fnp;
  float mn_ = (s0 - s1) / fnn;

  // CG state (thread d owns component d); solve M x = 1 for pos & neg systems
  float xp = 0.f, xn = 0.f, rp = 1.f, rn = 1.f, pp = 1.f, pn = 1.f;
  float rsp = (float)ND, rsn = (float)ND;
  float psp = (float)ND, psn = (float)ND;   // ||p||^2 (exact for p0 = ones)

  float v8[8], o8[8];
  #pragma unroll
  for (int i = 0; i < 8; i++) v8[i] = 0.f;
  v8[0] = mt; v8[1] = mp_; v8[2] = mn_;
  redK<8>(s_red, v8, o8, lane, w, tid);   // barriers fence s_idx/s_cp/s_cn/cache
  float sigt = o8[0], sigp = o8[1], sign_ = o8[2];
  // mu.p for each system (p0 = ones)
  float mtp = sigt, mpp = sigp, mtn = sigt, mnn = sign_;

  int ntiles = (ns + 15) >> 4;   // 16 rows per "tile" (1 row per warp)

  for (int it = 0; it < ITMAX; ++it) {
    // publish search directions
    s_pp[tid] = pp; s_pn[tid] = pn;
    __syncthreads();

    // p slices in packed u64 pairs
    u64 pp2[8], pn2[8];
    #pragma unroll
    for (int k = 0; k < 4; k++) {
      ulonglong2 a = ((const ulonglong2*)s_pp)[lane + 32 * k];
      ulonglong2 c = ((const ulonglong2*)s_pn)[lane + 32 * k];
      pp2[2 * k] = a.x; pp2[2 * k + 1] = a.y;
      pn2[2 * k] = c.x; pn2[2 * k + 1] = c.y;
    }

    // per-thread packed partial-Ap accumulators + warp p.(A_data p) scalars
    u64 accp2[8], accn2[8];
    #pragma unroll
    for (int k = 0; k < 8; k++) { accp2[k] = 0ull; accn2[k] = 0ull; }
    float scp = 0.f, scn = 0.f;   // sum_j c_j d_j^2 (warp partial, lane-redundant)

    // barrier-free row loop: warp w handles rows w, w+16, w+32, ...
    for (int t = 0; t < ntiles; t++) {
      int j = t * 16 + w;
      if (j < ns) {                       // warp-uniform branch
        u64 xv2[8];
        if (j < CROWS) {                  // warp-uniform
          const ulonglong2* row2 = (const ulonglong2*)(s_cache + (size_t)j * ND);
          #pragma unroll
          for (int k = 0; k < 4; k++) {
            ulonglong2 v = row2[lane + 32 * k];
            xv2[2 * k] = v.x; xv2[2 * k + 1] = v.y;
          }
        } else if (j < CROWS + RROWS) {   // register-cached (j == jreg here)
          #pragma unroll
          for (int k = 0; k < 8; k++) xv2[k] = xr2[k];
        } else {
          const ulonglong2* row2 = (const ulonglong2*)(X + (size_t)s_idx[j] * ND);
          #pragma unroll
          for (int k = 0; k < 4; k++) {
            ulonglong2 v = __ldg(&row2[lane + 32 * k]);
            xv2[2 * k] = v.x; xv2[2 * k + 1] = v.y;
          }
        }
        // packed dot products (8 FFMA2 per system)
        u64 dp2 = 0ull, dn2 = 0ull;
        #pragma unroll
        for (int k = 0; k < 8; k++) {
          dp2 = fma2(xv2[k], pp2[k], dp2);
          dn2 = fma2(xv2[k], pn2[k], dn2);
        }
        float2 fp = unpack2(dp2), fn = unpack2(dn2);
        float ap = fp.x + fp.y, an = fn.x + fn.y;
        // butterfly: all lanes end with the row sum
        #pragma unroll
        for (int o = 16; o; o >>= 1) {
          ap += __shfl_xor_sync(0xffffffffu, ap, o);
          an += __shfl_xor_sync(0xffffffffu, an, o);
        }
        float ep = s_cp[j] * ap;          // broadcast smem read
        float en = s_cn[j] * an;
        scp += ep * ap;                   // c_j d_j^2
        scn += en * an;
        u64 e2p = pack2(ep, ep), e2n = pack2(en, en);
        // packed rank-1 accumulate (8 FFMA2 per system)
        #pragma unroll
        for (int k = 0; k < 8; k++) {
          accp2[k] = fma2(e2p, xv2[k], accp2[k]);
          accn2[k] = fma2(e2n, xv2[k], accn2[k]);
        }
      }
    }

    // s_part round P + warp scalars share one barrier.
    #pragma unroll
    for (int k = 0; k < 4; k++)
      ((ulonglong2*)(s_part + (size_t)w * ND))[lane + 32 * k] =
          make_ulonglong2(accp2[2 * k], accp2[2 * k + 1]);
    if (lane == 0) { s_scal[w] = scp; s_scal[16 + w] = scn; }
    __syncthreads();
    float apr = 0.f;
    #pragma unroll
    for (int w2 = 0; w2 < 16; w2++) apr += s_part[(size_t)w2 * ND + tid];
    // p.q from warp scalars (identical deterministic sum on every thread)
    float pqp = 0.f, pqn = 0.f;
    #pragma unroll
    for (int w2 = 0; w2 < 16; w2++) { pqp += s_scal[w2]; pqn += s_scal[16 + w2]; }
    pqp += 0.1f * psp - wmt * mtp * mtp - wmp * mpp * mpp;
    pqn += 0.1f * psn - wmt * mtn * mtn - wmn * mnn * mnn;
    float alp = rsp / pqp, aln = rsn / pqn;
    float qp = apr + 0.1f * pp - wmt * mtp * mt - wmp * mpp * mp_;
    xp += alp * pp;  rp -= alp * qp;
    __syncthreads();                    // apr/s_scal reads done before round N
    #pragma unroll
    for (int k = 0; k < 4; k++)
      ((ulonglong2*)(s_part + (size_t)w * ND))[lane + 32 * k] =
          make_ulonglong2(accn2[2 * k], accn2[2 * k + 1]);
    __syncthreads();
    float anr = 0.f;
    #pragma unroll
    for (int w2 = 0; w2 < 16; w2++) anr += s_part[(size_t)w2 * ND + tid];
    float qn = anr + 0.1f * pn - wmt * mtn * mt - wmn * mnn * mn_;
    xn += aln * pn;  rn -= aln * qn;

    // tail reduction: {||r||^2, mu.r (fresh), ||p_old||^2} for both systems
    v8[0] = rp * rp; v8[1] = rn * rn;
    v8[2] = mt * rp; v8[3] = mp_ * rp;
    v8[4] = mt * rn; v8[5] = mn_ * rn;
    v8[6] = pp * pp; v8[7] = pn * pn;
    redK<8>(s_red, v8, o8, lane, w, tid);
    float bp = o8[0] / rsp, bn = o8[1] / rsn;
    rsp = o8[0]; rsn = o8[1];
    // ||p_new||^2 = ||r_new||^2 + beta^2 * ||p_old||^2 (r_new ⊥ p_old)
    psp = rsp + bp * bp * o8[6];
    psn = rsn + bn * bn * o8[7];
    pp = rp + bp * pp;  pn = rn + bn * pn;
    // mu.p_new = mu.r_new (fresh) + beta * mu.p_old  (exact identity)
    mtp = o8[2] + bp * mtp;  mpp = o8[3] + bp * mpp;
    mtn = o8[4] + bn * mtn;  mnn = o8[5] + bn * mnn;
    if (rsp < CG_TOL && rsn < CG_TOL) break;   // uniform across CTA
  }

  g_rr[b][0][tid] = xp;
  g_rr[b][1][tid] = xn;
  #pragma unroll
  for (int i = 0; i < 8; i++) v8[i] = 0.f;
  v8[0] = mp_ * xp; v8[1] = mn_ * xn;
  redK<8>(s_red, v8, o8, lane, w, tid);
  if (tid == 0) {
    g_sc[b][0] = o8[0]; g_sc[b][1] = sigp;
    g_sc[b][2] = o8[1]; g_sc[b][3] = sign_;
  }
}

// ---------------------------------------------------------------------------
// Kernel 4: outputs. maha = (q.r - mu.r) * (sum(q) - sum(mu)).
// grid (NB, 8) x 512 threads, float4 loads.
// ---------------------------------------------------------------------------
__global__ void out_kernel(const float* __restrict__ X, const float* __restrict__ log_scale,
                           float* __restrict__ out) {
  __shared__ float s_rp[ND];
  __shared__ float s_rn[ND];
  __shared__ float s_s[8];
  int b = blockIdx.x, part = blockIdx.y, tid = threadIdx.x;
  s_rp[tid] = g_rr[b][0][tid];
  s_rn[tid] = g_rr[b][1][tid];
  if (tid < 4) s_s[tid] = g_sc[b][tid];
  if (tid == 4) s_s[4] = expf(log_scale[0]);
  __syncthreads();
  int nq = g_cnt[b][2];
  int w = tid >> 5, lane = tid & 31;
  const float4* rp4 = (const float4*)s_rp;
  const float4* rn4 = (const float4*)s_rn;
  #pragma unroll
  for (int rep = 0; rep < 4; rep++) {
    int i = part * 64 + rep * 16 + w;
    if (i < nq) {
      int gj = g_qry_idx[b][i];
      const float4* q4 = (const float4*)(X + (size_t)gj * ND);
      float aqr = 0.f, aqn = 0.f, aqs = 0.f;
      #pragma unroll
      for (int k = 0; k < 4; k++) {
        float4 v = q4[lane + 32 * k];
        float4 a = rp4[lane + 32 * k];
        float4 c = rn4[lane + 32 * k];
        aqr += v.x * a.x + v.y * a.y + v.z * a.z + v.w * a.w;
        aqn += v.x * c.x + v.y * c.y + v.z * c.z + v.w * c.w;
        aqs += v.x + v.y + v.z + v.w;
      }
      #pragma unroll
      for (int o = 16; o; o >>= 1) {
        aqr += __shfl_down_sync(0xffffffffu, aqr, o);
        aqn += __shfl_down_sync(0xffffffffu, aqn, o);
        aqs += __shfl_down_sync(0xffffffffu, aqs, o);
      }
      if (lane == 0) {
        float sc = s_s[4];
        float sp = aqr - s_s[0], tp = aqs - s_s[1];
        float sn = aqn - s_s[2], tn = aqs - s_s[3];
        size_t o0 = ((size_t)b * NL + i) * 2;
        out[o0]     = sn * tn * sc;   // neg logit
        out[o0 + 1] = sp * tp * sc;   // pos logit
      }
    } else if (lane == 0) {
      size_t o0 = ((size_t)b * NL + i) * 2;
      out[o0] = 0.f; out[o0 + 1] = 0.f;
    }
  }
}

// ---------------------------------------------------------------------------
// Inputs (metadata order): graph_reprs f32[N*512], log_scale f32[1],
// labels i32[N], is_query i32[N], batch_index i32[N] (sorted).
// Output: f32[128*512*2].
// ---------------------------------------------------------------------------
extern "C" void kernel_launch(void* const* d_in, const int* in_sizes, int n_in,
                              void* d_out, int out_size) {
  const float* X      = (const float*)d_in[0];
  const float* logsc  = (const float*)d_in[1];
  const int*   labels = (const int*)d_in[2];
  const int*   isq    = (const int*)d_in[3];
  const int*   bidx   = (const int*)d_in[4];
  int N = in_sizes[2];

  cudaFuncSetAttribute(cg_kernel, cudaFuncAttributeMaxDynamicSharedMemorySize, CG_SMEM_BYTES);

  seg_kernel<<<NB, 32>>>(bidx, isq, labels, N);
  mean_kernel<<<dim3(NB, NPART), ND>>>(X);
  cg_kernel<<<NB, ND, CG_SMEM_BYTES>>>(X);
  out_kernel<<<dim3(NB, 8), 512>>>(X, logsc, (float*)d_out);
}